// round 14
// baseline (speedup 1.0000x reference)
#include <cuda_runtime.h>
#include <cuda_bf16.h>
#include <cstdint>

#define BATCH 4
#define S_LEN 2048
#define HDIM  1024
#define NHQ   16
#define NKV   4
#define HD    64
#define SCALE 0.125f

// ---------------- device scratch (no cudaMalloc allowed) ----------------
__device__ float g_Q[(size_t)BATCH * NHQ * S_LEN * HD];    // [b, h, s, d]
__device__ float g_K[(size_t)BATCH * NKV * S_LEN * HD];    // [b, kvh, s, d]
__device__ float g_V[(size_t)BATCH * NKV * S_LEN * HD];    // [b, kvh, s, d]
__device__ float g_attn[(size_t)BATCH * S_LEN * NHQ * HD]; // [b, s, h*HD]

__device__ __align__(16) __nv_bfloat16 g_Xhi[(size_t)BATCH * S_LEN * HDIM];
__device__ __align__(16) __nv_bfloat16 g_Xlo[(size_t)BATCH * S_LEN * HDIM];
__device__ __align__(16) __nv_bfloat16 g_Ahi[(size_t)BATCH * S_LEN * HDIM];
__device__ __align__(16) __nv_bfloat16 g_Alo[(size_t)BATCH * S_LEN * HDIM];
__device__ __align__(16) __nv_bfloat16 g_Wqt_hi[(size_t)HDIM * HDIM];
__device__ __align__(16) __nv_bfloat16 g_Wqt_lo[(size_t)HDIM * HDIM];
__device__ __align__(16) __nv_bfloat16 g_Wkt_hi[(size_t)256 * HDIM];
__device__ __align__(16) __nv_bfloat16 g_Wkt_lo[(size_t)256 * HDIM];
__device__ __align__(16) __nv_bfloat16 g_Wvt_hi[(size_t)256 * HDIM];
__device__ __align__(16) __nv_bfloat16 g_Wvt_lo[(size_t)256 * HDIM];
__device__ __align__(16) __nv_bfloat16 g_Wot_hi[(size_t)HDIM * HDIM];
__device__ __align__(16) __nv_bfloat16 g_Wot_lo[(size_t)HDIM * HDIM];

// ---------------- bf16 mma.sync helper (legacy path, compiles on sm_103) --
__device__ __forceinline__ void mma_bf16(float c[4], const uint32_t a[4],
                                         uint32_t b0, uint32_t b1) {
    asm volatile(
        "mma.sync.aligned.m16n8k16.row.col.f32.bf16.bf16.f32 "
        "{%0,%1,%2,%3},{%4,%5,%6,%7},{%8,%9},{%0,%1,%2,%3};"
        : "+f"(c[0]), "+f"(c[1]), "+f"(c[2]), "+f"(c[3])
        : "r"(a[0]), "r"(a[1]), "r"(a[2]), "r"(a[3]), "r"(b0), "r"(b1));
}

// ---------------- 128x128 GEMM, 3-term bf16, K=1024 fixed -----------------
// C[M,N] = A[M,K] * Bt[N,K]^T with A = Ahi+Alo, B = Bhi+Blo (pre-split bf16)
// scatter==1: C is [b, head, s, d] (QKV projections); else row-major MxN.
#define SSTR 40   // smem row stride in halfwords (80 B): conflict-free frags

__global__ __launch_bounds__(256) void gemm_bf16_kernel(
    const __nv_bfloat16* __restrict__ Ahi, const __nv_bfloat16* __restrict__ Alo,
    const __nv_bfloat16* __restrict__ Bhi, const __nv_bfloat16* __restrict__ Blo,
    float* __restrict__ C, int N, int scatter, int heads)
{
    __shared__ __nv_bfloat16 sAh[128][SSTR], sAl[128][SSTR];
    __shared__ __nv_bfloat16 sBh[128][SSTR], sBl[128][SSTR];

    const int tid = threadIdx.x;
    const int lane = tid & 31, warp = tid >> 5;
    const int wm = warp & 3;     // 4 warps along M: 32 rows each
    const int wn = warp >> 2;    // 2 warps along N: 64 cols each
    const int bm = blockIdx.y << 7;
    const int bn = blockIdx.x << 7;

    // staging map: each thread owns row sr, halfword cols sc..sc+15 (two uint4)
    const int sr = tid >> 1;
    const int sc = (tid & 1) << 4;

    float acc[2][8][4];
#pragma unroll
    for (int mt = 0; mt < 2; mt++)
#pragma unroll
        for (int nt = 0; nt < 8; nt++)
#pragma unroll
            for (int e = 0; e < 4; e++) acc[mt][nt][e] = 0.f;

    const size_t aoff = (size_t)(bm + sr) * HDIM + sc;
    const size_t boff = (size_t)(bn + sr) * HDIM + sc;

    uint4 pAh[2], pAl[2], pBh[2], pBl[2];
    pAh[0] = *(const uint4*)(Ahi + aoff); pAh[1] = *(const uint4*)(Ahi + aoff + 8);
    pAl[0] = *(const uint4*)(Alo + aoff); pAl[1] = *(const uint4*)(Alo + aoff + 8);
    pBh[0] = *(const uint4*)(Bhi + boff); pBh[1] = *(const uint4*)(Bhi + boff + 8);
    pBl[0] = *(const uint4*)(Blo + boff); pBl[1] = *(const uint4*)(Blo + boff + 8);

    for (int k0 = 0; k0 < HDIM; k0 += 32) {
        // stage prefetched registers -> smem
        *(uint4*)(&sAh[sr][sc]) = pAh[0]; *(uint4*)(&sAh[sr][sc + 8]) = pAh[1];
        *(uint4*)(&sAl[sr][sc]) = pAl[0]; *(uint4*)(&sAl[sr][sc + 8]) = pAl[1];
        *(uint4*)(&sBh[sr][sc]) = pBh[0]; *(uint4*)(&sBh[sr][sc + 8]) = pBh[1];
        *(uint4*)(&sBl[sr][sc]) = pBl[0]; *(uint4*)(&sBl[sr][sc + 8]) = pBl[1];
        __syncthreads();

        if (k0 + 32 < HDIM) {  // prefetch next chunk
            const size_t na = aoff + k0 + 32, nb = boff + k0 + 32;
            pAh[0] = *(const uint4*)(Ahi + na); pAh[1] = *(const uint4*)(Ahi + na + 8);
            pAl[0] = *(const uint4*)(Alo + na); pAl[1] = *(const uint4*)(Alo + na + 8);
            pBh[0] = *(const uint4*)(Bhi + nb); pBh[1] = *(const uint4*)(Bhi + nb + 8);
            pBl[0] = *(const uint4*)(Blo + nb); pBl[1] = *(const uint4*)(Blo + nb + 8);
        }

#pragma unroll
        for (int ks = 0; ks < 32; ks += 16) {
            const int ca = ks + (lane & 3) * 2;
            uint32_t ah[2][4], al[2][4];
#pragma unroll
            for (int mt = 0; mt < 2; mt++) {
                const int r = wm * 32 + mt * 16 + (lane >> 2);
                ah[mt][0] = *(const uint32_t*)(&sAh[r][ca]);
                ah[mt][1] = *(const uint32_t*)(&sAh[r + 8][ca]);
                ah[mt][2] = *(const uint32_t*)(&sAh[r][ca + 8]);
                ah[mt][3] = *(const uint32_t*)(&sAh[r + 8][ca + 8]);
                al[mt][0] = *(const uint32_t*)(&sAl[r][ca]);
                al[mt][1] = *(const uint32_t*)(&sAl[r + 8][ca]);
                al[mt][2] = *(const uint32_t*)(&sAl[r][ca + 8]);
                al[mt][3] = *(const uint32_t*)(&sAl[r + 8][ca + 8]);
            }
#pragma unroll
            for (int nt = 0; nt < 8; nt++) {
                const int n = wn * 64 + nt * 8 + (lane >> 2);
                const uint32_t bh0 = *(const uint32_t*)(&sBh[n][ca]);
                const uint32_t bh1 = *(const uint32_t*)(&sBh[n][ca + 8]);
                const uint32_t bl0 = *(const uint32_t*)(&sBl[n][ca]);
                const uint32_t bl1 = *(const uint32_t*)(&sBl[n][ca + 8]);
#pragma unroll
                for (int mt = 0; mt < 2; mt++) {
                    mma_bf16(acc[mt][nt], ah[mt], bl0, bl1);  // small terms first
                    mma_bf16(acc[mt][nt], al[mt], bh0, bh1);
                    mma_bf16(acc[mt][nt], ah[mt], bh0, bh1);
                }
            }
        }
        __syncthreads();
    }

    // epilogue (fragment layout identical to m16n8k8: c0,c1 @ row r; c2,c3 @ r+8)
#pragma unroll
    for (int mt = 0; mt < 2; mt++) {
#pragma unroll
        for (int nt = 0; nt < 8; nt++) {
            const int r0 = bm + wm * 32 + mt * 16 + (lane >> 2);
            const int cn = bn + wn * 64 + nt * 8 + (lane & 3) * 2;
            if (scatter) {
                const int head = cn >> 6, d = cn & 63;
#pragma unroll
                for (int half = 0; half < 2; half++) {
                    const int rm = r0 + half * 8;
                    const int b = rm >> 11, s = rm & 2047;
                    float* dst = C + (((size_t)(b * heads + head)) * S_LEN + s) * HD + d;
                    *(float2*)dst = make_float2(acc[mt][nt][half * 2], acc[mt][nt][half * 2 + 1]);
                }
            } else {
                *(float2*)(C + (size_t)r0 * N + cn) =
                    make_float2(acc[mt][nt][0], acc[mt][nt][1]);
                *(float2*)(C + (size_t)(r0 + 8) * N + cn) =
                    make_float2(acc[mt][nt][2], acc[mt][nt][3]);
            }
        }
    }
}

// ---------------- fp32 -> bf16 hi/lo split ----------------
__global__ __launch_bounds__(256) void split_kernel(
    const float* __restrict__ X, __nv_bfloat16* __restrict__ Hi,
    __nv_bfloat16* __restrict__ Lo, int n4)
{
    const int i = blockIdx.x * 256 + threadIdx.x;
    if (i >= n4) return;
    const float4 v = ((const float4*)X)[i];
    float x[4] = {v.x, v.y, v.z, v.w};
    __nv_bfloat16 h[4], l[4];
#pragma unroll
    for (int e = 0; e < 4; e++) {
        h[e] = __float2bfloat16(x[e]);
        l[e] = __float2bfloat16(x[e] - __bfloat162float(h[e]));
    }
    ((__nv_bfloat162*)Hi)[2 * i]     = __nv_bfloat162(h[0], h[1]);
    ((__nv_bfloat162*)Hi)[2 * i + 1] = __nv_bfloat162(h[2], h[3]);
    ((__nv_bfloat162*)Lo)[2 * i]     = __nv_bfloat162(l[0], l[1]);
    ((__nv_bfloat162*)Lo)[2 * i + 1] = __nv_bfloat162(l[2], l[3]);
}

// ---------------- W[K,N] fp32 -> Wt[N,K] bf16 hi/lo (transpose+split) ------
__global__ __launch_bounds__(256) void transpose_split_kernel(
    const float* __restrict__ W, __nv_bfloat16* __restrict__ Thi,
    __nv_bfloat16* __restrict__ Tlo, int K, int N)
{
    __shared__ float t[32][33];
    const int k0 = blockIdx.y * 32, n0 = blockIdx.x * 32;
    const int tx = threadIdx.x, ty = threadIdx.y;   // 32 x 8
#pragma unroll
    for (int i = 0; i < 32; i += 8)
        t[ty + i][tx] = W[(size_t)(k0 + ty + i) * N + n0 + tx];
    __syncthreads();
#pragma unroll
    for (int i = 0; i < 32; i += 8) {
        const float x = t[tx][ty + i];
        const __nv_bfloat16 h = __float2bfloat16(x);
        const __nv_bfloat16 l = __float2bfloat16(x - __bfloat162float(h));
        Thi[(size_t)(n0 + ty + i) * K + k0 + tx] = h;
        Tlo[(size_t)(n0 + ty + i) * K + k0 + tx] = l;
    }
}

// ---------------- RMSNorm + interleaved RoPE ----------------
__global__ __launch_bounds__(256) void norm_rope_kernel(
    float* __restrict__ X, const float* __restrict__ w,
    const float* __restrict__ cosb, const float* __restrict__ sinb, int rows)
{
    const int row = blockIdx.x * 8 + threadIdx.y;
    if (row >= rows) return;
    const int lane = threadIdx.x;
    const int s = row & (S_LEN - 1);

    float2 x = *(float2*)(X + (size_t)row * HD + lane * 2);
    float ssq = x.x * x.x + x.y * x.y;
#pragma unroll
    for (int m = 16; m; m >>= 1) ssq += __shfl_xor_sync(0xffffffffu, ssq, m);
    const float inv = rsqrtf(ssq * (1.0f / 64.0f) + 1e-6f);

    const float n0 = x.x * inv * w[lane * 2];
    const float n1 = x.y * inv * w[lane * 2 + 1];
    const float c0 = cosb[(size_t)s * HD + lane * 2];
    const float c1 = cosb[(size_t)s * HD + lane * 2 + 1];
    const float s0 = sinb[(size_t)s * HD + lane * 2];
    const float s1 = sinb[(size_t)s * HD + lane * 2 + 1];

    float2 o;
    o.x = n0 * c0 - n1 * s0;
    o.y = n1 * c1 + n0 * s1;
    *(float2*)(X + (size_t)row * HD + lane * 2) = o;
}

// ---------------- flash attention (causal, GQA), fp32 ----------------
__global__ __launch_bounds__(256) void flash_kernel(
    const float* __restrict__ Q, const float* __restrict__ K,
    const float* __restrict__ V, float* __restrict__ O)
{
    __shared__ float QsT[64][64];
    __shared__ float KsT[64][64];
    __shared__ float Vs[64][64];
    float (*Ps)[64] = KsT;

    const int bh = blockIdx.y;
    const int b = bh >> 4, h = bh & 15, kvh = (bh & 15) >> 2;
    const int i0 = blockIdx.x << 6;
    const float* Qb = Q + ((size_t)(b * NHQ + h) * S_LEN + i0) * HD;
    const float* Kb = K + (size_t)(b * NKV + kvh) * S_LEN * HD;
    const float* Vb = V + (size_t)(b * NKV + kvh) * S_LEN * HD;

    const int tid = threadIdx.x;
    const int tx = tid & 15, ty = tid >> 4;
    const int r0 = ty << 2, c0 = tx << 2;

    for (int idx = tid; idx < 1024; idx += 256) {
        const int r = idx >> 4, d = (idx & 15) << 2;
        float4 v = *(const float4*)(Qb + (size_t)r * HD + d);
        QsT[d][r] = v.x; QsT[d + 1][r] = v.y; QsT[d + 2][r] = v.z; QsT[d + 3][r] = v.w;
    }

    float m_i[4] = {-1e30f, -1e30f, -1e30f, -1e30f};
    float l_i[4] = {0.f, 0.f, 0.f, 0.f};
    float oa[4][4];
#pragma unroll
    for (int i = 0; i < 4; i++)
#pragma unroll
        for (int j = 0; j < 4; j++) oa[i][j] = 0.f;

    const int ntiles = blockIdx.x + 1;
    for (int t = 0; t < ntiles; t++) {
        const int j0 = t << 6;
        __syncthreads();
        for (int idx = tid; idx < 1024; idx += 256) {
            const int r = idx >> 4, d = (idx & 15) << 2;
            float4 kv = *(const float4*)(Kb + (size_t)(j0 + r) * HD + d);
            KsT[d][r] = kv.x; KsT[d + 1][r] = kv.y; KsT[d + 2][r] = kv.z; KsT[d + 3][r] = kv.w;
            *(float4*)(&Vs[r][d]) = *(const float4*)(Vb + (size_t)(j0 + r) * HD + d);
        }
        __syncthreads();

        float sc[4][4];
#pragma unroll
        for (int i = 0; i < 4; i++)
#pragma unroll
            for (int j = 0; j < 4; j++) sc[i][j] = 0.f;
#pragma unroll 8
        for (int d = 0; d < 64; d++) {
            float4 aq = *(const float4*)(&QsT[d][r0]);
            float4 bk = *(const float4*)(&KsT[d][c0]);
            sc[0][0] += aq.x * bk.x; sc[0][1] += aq.x * bk.y; sc[0][2] += aq.x * bk.z; sc[0][3] += aq.x * bk.w;
            sc[1][0] += aq.y * bk.x; sc[1][1] += aq.y * bk.y; sc[1][2] += aq.y * bk.z; sc[1][3] += aq.y * bk.w;
            sc[2][0] += aq.z * bk.x; sc[2][1] += aq.z * bk.y; sc[2][2] += aq.z * bk.z; sc[2][3] += aq.z * bk.w;
            sc[3][0] += aq.w * bk.x; sc[3][1] += aq.w * bk.y; sc[3][2] += aq.w * bk.z; sc[3][3] += aq.w * bk.w;
        }
        __syncthreads();

        const bool diag = (t == (int)blockIdx.x);
#pragma unroll
        for (int i = 0; i < 4; i++) {
#pragma unroll
            for (int j = 0; j < 4; j++) {
                float s = sc[i][j] * SCALE;
                if (diag && (c0 + j > r0 + i)) s = -1e9f;
                sc[i][j] = s;
            }
            float mt = fmaxf(fmaxf(sc[i][0], sc[i][1]), fmaxf(sc[i][2], sc[i][3]));
            mt = fmaxf(mt, __shfl_xor_sync(0xffffffffu, mt, 8));
            mt = fmaxf(mt, __shfl_xor_sync(0xffffffffu, mt, 4));
            mt = fmaxf(mt, __shfl_xor_sync(0xffffffffu, mt, 2));
            mt = fmaxf(mt, __shfl_xor_sync(0xffffffffu, mt, 1));
            const float m_new = fmaxf(m_i[i], mt);
            const float corr = __expf(m_i[i] - m_new);
            m_i[i] = m_new;
            float ps = 0.f;
#pragma unroll
            for (int j = 0; j < 4; j++) {
                const float p = __expf(sc[i][j] - m_new);
                sc[i][j] = p;
                ps += p;
            }
            ps += __shfl_xor_sync(0xffffffffu, ps, 8);
            ps += __shfl_xor_sync(0xffffffffu, ps, 4);
            ps += __shfl_xor_sync(0xffffffffu, ps, 2);
            ps += __shfl_xor_sync(0xffffffffu, ps, 1);
            l_i[i] = l_i[i] * corr + ps;
#pragma unroll
            for (int j = 0; j < 4; j++) oa[i][j] *= corr;
            *(float4*)(&Ps[r0 + i][c0]) = *(float4*)(&sc[i][0]);
        }
        __syncthreads();

#pragma unroll 8
        for (int k = 0; k < 64; k++) {
            float4 vv = *(const float4*)(&Vs[k][c0]);
#pragma unroll
            for (int i = 0; i < 4; i++) {
                const float p = Ps[r0 + i][k];
                oa[i][0] += p * vv.x; oa[i][1] += p * vv.y;
                oa[i][2] += p * vv.z; oa[i][3] += p * vv.w;
            }
        }
    }

#pragma unroll
    for (int i = 0; i < 4; i++) {
        const float inv = 1.0f / l_i[i];
        float* dst = O + ((size_t)b * S_LEN + i0 + r0 + i) * (NHQ * HD) + h * HD + c0;
        *(float4*)dst = make_float4(oa[i][0] * inv, oa[i][1] * inv,
                                    oa[i][2] * inv, oa[i][3] * inv);
    }
}

// ---------------- launch ----------------
extern "C" void kernel_launch(void* const* d_in, const int* in_sizes, int n_in,
                              void* d_out, int out_size)
{
    const float* X    = (const float*)d_in[0];
    const float* cosb = (const float*)d_in[2];
    const float* sinb = (const float*)d_in[3];
    const float* Wq   = (const float*)d_in[4];
    const float* Wk   = (const float*)d_in[5];
    const float* Wv   = (const float*)d_in[6];
    const float* Wo   = (const float*)d_in[7];
    const float* qw   = (const float*)d_in[8];
    const float* kw   = (const float*)d_in[9];
    float* out = (float*)d_out;

    void *pQ, *pK, *pV, *pA;
    void *pXhi, *pXlo, *pAhi, *pAlo;
    void *pWq_h, *pWq_l, *pWk_h, *pWk_l, *pWv_h, *pWv_l, *pWo_h, *pWo_l;
    cudaGetSymbolAddress(&pQ, g_Q);
    cudaGetSymbolAddress(&pK, g_K);
    cudaGetSymbolAddress(&pV, g_V);
    cudaGetSymbolAddress(&pA, g_attn);
    cudaGetSymbolAddress(&pXhi, g_Xhi);
    cudaGetSymbolAddress(&pXlo, g_Xlo);
    cudaGetSymbolAddress(&pAhi, g_Ahi);
    cudaGetSymbolAddress(&pAlo, g_Alo);
    cudaGetSymbolAddress(&pWq_h, g_Wqt_hi);
    cudaGetSymbolAddress(&pWq_l, g_Wqt_lo);
    cudaGetSymbolAddress(&pWk_h, g_Wkt_hi);
    cudaGetSymbolAddress(&pWk_l, g_Wkt_lo);
    cudaGetSymbolAddress(&pWv_h, g_Wvt_hi);
    cudaGetSymbolAddress(&pWv_l, g_Wvt_lo);
    cudaGetSymbolAddress(&pWo_h, g_Wot_hi);
    cudaGetSymbolAddress(&pWo_l, g_Wot_lo);

    const int M = BATCH * S_LEN;          // 8192
    const int n4 = M * HDIM / 4;          // float4 count

    // splits / transposes
    split_kernel<<<(n4 + 255) / 256, 256>>>(X, (__nv_bfloat16*)pXhi, (__nv_bfloat16*)pXlo, n4);
    transpose_split_kernel<<<dim3(HDIM / 32, HDIM / 32), dim3(32, 8)>>>(Wq, (__nv_bfloat16*)pWq_h, (__nv_bfloat16*)pWq_l, HDIM, HDIM);
    transpose_split_kernel<<<dim3(256 / 32, HDIM / 32), dim3(32, 8)>>>(Wk, (__nv_bfloat16*)pWk_h, (__nv_bfloat16*)pWk_l, HDIM, 256);
    transpose_split_kernel<<<dim3(256 / 32, HDIM / 32), dim3(32, 8)>>>(Wv, (__nv_bfloat16*)pWv_h, (__nv_bfloat16*)pWv_l, HDIM, 256);
    transpose_split_kernel<<<dim3(HDIM / 32, HDIM / 32), dim3(32, 8)>>>(Wo, (__nv_bfloat16*)pWo_h, (__nv_bfloat16*)pWo_l, HDIM, HDIM);

    // QKV projections (bf16 mma.sync), scatter into [b, head, s, d]
    gemm_bf16_kernel<<<dim3(NHQ * HD / 128, M / 128), 256>>>(
        (const __nv_bfloat16*)pXhi, (const __nv_bfloat16*)pXlo,
        (const __nv_bfloat16*)pWq_h, (const __nv_bfloat16*)pWq_l,
        (float*)pQ, NHQ * HD, 1, NHQ);
    gemm_bf16_kernel<<<dim3(NKV * HD / 128, M / 128), 256>>>(
        (const __nv_bfloat16*)pXhi, (const __nv_bfloat16*)pXlo,
        (const __nv_bfloat16*)pWk_h, (const __nv_bfloat16*)pWk_l,
        (float*)pK, NKV * HD, 1, NKV);
    gemm_bf16_kernel<<<dim3(NKV * HD / 128, M / 128), 256>>>(
        (const __nv_bfloat16*)pXhi, (const __nv_bfloat16*)pXlo,
        (const __nv_bfloat16*)pWv_h, (const __nv_bfloat16*)pWv_l,
        (float*)pV, NKV * HD, 1, NKV);

    // RMSNorm + RoPE
    norm_rope_kernel<<<(BATCH * NHQ * S_LEN) / 8, dim3(32, 8)>>>((float*)pQ, qw, cosb, sinb, BATCH * NHQ * S_LEN);
    norm_rope_kernel<<<(BATCH * NKV * S_LEN) / 8, dim3(32, 8)>>>((float*)pK, kw, cosb, sinb, BATCH * NKV * S_LEN);

    // flash attention (fp32)
    flash_kernel<<<dim3(S_LEN / 64, BATCH * NHQ), 256>>>((const float*)pQ, (const float*)pK, (const float*)pV, (float*)pA);

    // split attn, then O-projection (bf16 mma.sync)
    split_kernel<<<(n4 + 255) / 256, 256>>>((const float*)pA, (__nv_bfloat16*)pAhi, (__nv_bfloat16*)pAlo, n4);
    gemm_bf16_kernel<<<dim3(HDIM / 128, M / 128), 256>>>(
        (const __nv_bfloat16*)pAhi, (const __nv_bfloat16*)pAlo,
        (const __nv_bfloat16*)pWo_h, (const __nv_bfloat16*)pWo_l,
        out, HDIM, 0, 0);
}

// round 15
// speedup vs baseline: 1.8014x; 1.8014x over previous
#include <cuda_runtime.h>
#include <cuda_bf16.h>
#include <cstdint>

#define BATCH 4
#define S_LEN 2048
#define HDIM  1024
#define NHQ   16
#define NKV   4
#define HD    64

// ---------------- device scratch (no cudaMalloc allowed) ----------------
__device__ float g_Q[(size_t)BATCH * NHQ * S_LEN * HD];    // [b, h, s, d]
__device__ float g_K[(size_t)BATCH * NKV * S_LEN * HD];    // [b, kvh, s, d]
__device__ float g_V[(size_t)BATCH * NKV * S_LEN * HD];    // [b, kvh, s, d]
__device__ float g_attn[(size_t)BATCH * S_LEN * NHQ * HD]; // [b, s, h*HD]

__device__ __align__(16) __nv_bfloat16 g_Xhi[(size_t)BATCH * S_LEN * HDIM];
__device__ __align__(16) __nv_bfloat16 g_Xlo[(size_t)BATCH * S_LEN * HDIM];
__device__ __align__(16) __nv_bfloat16 g_Ahi[(size_t)BATCH * S_LEN * HDIM];  // Qhi, later attn-hi
__device__ __align__(16) __nv_bfloat16 g_Alo[(size_t)BATCH * S_LEN * HDIM];  // Qlo, later attn-lo
__device__ __align__(16) __nv_bfloat16 g_Khi[(size_t)BATCH * NKV * S_LEN * HD];
__device__ __align__(16) __nv_bfloat16 g_Klo[(size_t)BATCH * NKV * S_LEN * HD];
__device__ __align__(16) __nv_bfloat16 g_Vthi[(size_t)BATCH * NKV * HD * S_LEN]; // [b,kvh,d,s]
__device__ __align__(16) __nv_bfloat16 g_Vtlo[(size_t)BATCH * NKV * HD * S_LEN];
__device__ __align__(16) __nv_bfloat16 g_Wqt_hi[(size_t)HDIM * HDIM];
__device__ __align__(16) __nv_bfloat16 g_Wqt_lo[(size_t)HDIM * HDIM];
__device__ __align__(16) __nv_bfloat16 g_Wkt_hi[(size_t)256 * HDIM];
__device__ __align__(16) __nv_bfloat16 g_Wkt_lo[(size_t)256 * HDIM];
__device__ __align__(16) __nv_bfloat16 g_Wvt_hi[(size_t)256 * HDIM];
__device__ __align__(16) __nv_bfloat16 g_Wvt_lo[(size_t)256 * HDIM];
__device__ __align__(16) __nv_bfloat16 g_Wot_hi[(size_t)HDIM * HDIM];
__device__ __align__(16) __nv_bfloat16 g_Wot_lo[(size_t)HDIM * HDIM];

// ---------------- helpers ----------------
__device__ __forceinline__ void mma_bf16(float c[4], const uint32_t a[4],
                                         uint32_t b0, uint32_t b1) {
    asm volatile(
        "mma.sync.aligned.m16n8k16.row.col.f32.bf16.bf16.f32 "
        "{%0,%1,%2,%3},{%4,%5,%6,%7},{%8,%9},{%0,%1,%2,%3};"
        : "+f"(c[0]), "+f"(c[1]), "+f"(c[2]), "+f"(c[3])
        : "r"(a[0]), "r"(a[1]), "r"(a[2]), "r"(a[3]), "r"(b0), "r"(b1));
}
// pack two f32 -> bf16x2 (lo -> low half, hi -> high half)
__device__ __forceinline__ uint32_t packbf(float lo, float hi) {
    uint32_t r;
    asm("cvt.rn.bf16x2.f32 %0, %1, %2;" : "=r"(r) : "f"(hi), "f"(lo));
    return r;
}
// 2^x on the FMA pipe, x <= 0 expected; rel err ~1e-4
__device__ __forceinline__ float exp2p(float x) {
    x = fmaxf(x, -126.f);
    const float n = floorf(x);
    const float f = x - n;
    float p = 1.33335581e-3f;
    p = fmaf(p, f, 9.61812910e-3f);
    p = fmaf(p, f, 5.55041087e-2f);
    p = fmaf(p, f, 2.40226507e-1f);
    p = fmaf(p, f, 6.93147182e-1f);
    p = fmaf(p, f, 1.0f);
    return p * __int_as_float(((int)n + 127) << 23);
}

// ---------------- 128x128 GEMM, 3-term bf16, K=1024 fixed -----------------
#define SSTR 40

__global__ __launch_bounds__(256) void gemm_bf16_kernel(
    const __nv_bfloat16* __restrict__ Ahi, const __nv_bfloat16* __restrict__ Alo,
    const __nv_bfloat16* __restrict__ Bhi, const __nv_bfloat16* __restrict__ Blo,
    float* __restrict__ C, int N, int scatter, int heads)
{
    __shared__ __nv_bfloat16 sAh[128][SSTR], sAl[128][SSTR];
    __shared__ __nv_bfloat16 sBh[128][SSTR], sBl[128][SSTR];

    const int tid = threadIdx.x;
    const int lane = tid & 31, warp = tid >> 5;
    const int wm = warp & 3;
    const int wn = warp >> 2;
    const int bm = blockIdx.y << 7;
    const int bn = blockIdx.x << 7;

    const int sr = tid >> 1;
    const int sc = (tid & 1) << 4;

    float acc[2][8][4];
#pragma unroll
    for (int mt = 0; mt < 2; mt++)
#pragma unroll
        for (int nt = 0; nt < 8; nt++)
#pragma unroll
            for (int e = 0; e < 4; e++) acc[mt][nt][e] = 0.f;

    const size_t aoff = (size_t)(bm + sr) * HDIM + sc;
    const size_t boff = (size_t)(bn + sr) * HDIM + sc;

    uint4 pAh[2], pAl[2], pBh[2], pBl[2];
    pAh[0] = *(const uint4*)(Ahi + aoff); pAh[1] = *(const uint4*)(Ahi + aoff + 8);
    pAl[0] = *(const uint4*)(Alo + aoff); pAl[1] = *(const uint4*)(Alo + aoff + 8);
    pBh[0] = *(const uint4*)(Bhi + boff); pBh[1] = *(const uint4*)(Bhi + boff + 8);
    pBl[0] = *(const uint4*)(Blo + boff); pBl[1] = *(const uint4*)(Blo + boff + 8);

    for (int k0 = 0; k0 < HDIM; k0 += 32) {
        *(uint4*)(&sAh[sr][sc]) = pAh[0]; *(uint4*)(&sAh[sr][sc + 8]) = pAh[1];
        *(uint4*)(&sAl[sr][sc]) = pAl[0]; *(uint4*)(&sAl[sr][sc + 8]) = pAl[1];
        *(uint4*)(&sBh[sr][sc]) = pBh[0]; *(uint4*)(&sBh[sr][sc + 8]) = pBh[1];
        *(uint4*)(&sBl[sr][sc]) = pBl[0]; *(uint4*)(&sBl[sr][sc + 8]) = pBl[1];
        __syncthreads();

        if (k0 + 32 < HDIM) {
            const size_t na = aoff + k0 + 32, nb = boff + k0 + 32;
            pAh[0] = *(const uint4*)(Ahi + na); pAh[1] = *(const uint4*)(Ahi + na + 8);
            pAl[0] = *(const uint4*)(Alo + na); pAl[1] = *(const uint4*)(Alo + na + 8);
            pBh[0] = *(const uint4*)(Bhi + nb); pBh[1] = *(const uint4*)(Bhi + nb + 8);
            pBl[0] = *(const uint4*)(Blo + nb); pBl[1] = *(const uint4*)(Blo + nb + 8);
        }

#pragma unroll
        for (int ks = 0; ks < 32; ks += 16) {
            const int ca = ks + (lane & 3) * 2;
            uint32_t ah[2][4], al[2][4];
#pragma unroll
            for (int mt = 0; mt < 2; mt++) {
                const int r = wm * 32 + mt * 16 + (lane >> 2);
                ah[mt][0] = *(const uint32_t*)(&sAh[r][ca]);
                ah[mt][1] = *(const uint32_t*)(&sAh[r + 8][ca]);
                ah[mt][2] = *(const uint32_t*)(&sAh[r][ca + 8]);
                ah[mt][3] = *(const uint32_t*)(&sAh[r + 8][ca + 8]);
                al[mt][0] = *(const uint32_t*)(&sAl[r][ca]);
                al[mt][1] = *(const uint32_t*)(&sAl[r + 8][ca]);
                al[mt][2] = *(const uint32_t*)(&sAl[r][ca + 8]);
                al[mt][3] = *(const uint32_t*)(&sAl[r + 8][ca + 8]);
            }
#pragma unroll
            for (int nt = 0; nt < 8; nt++) {
                const int n = wn * 64 + nt * 8 + (lane >> 2);
                const uint32_t bh0 = *(const uint32_t*)(&sBh[n][ca]);
                const uint32_t bh1 = *(const uint32_t*)(&sBh[n][ca + 8]);
                const uint32_t bl0 = *(const uint32_t*)(&sBl[n][ca]);
                const uint32_t bl1 = *(const uint32_t*)(&sBl[n][ca + 8]);
#pragma unroll
                for (int mt = 0; mt < 2; mt++) {
                    mma_bf16(acc[mt][nt], ah[mt], bl0, bl1);
                    mma_bf16(acc[mt][nt], al[mt], bh0, bh1);
                    mma_bf16(acc[mt][nt], ah[mt], bh0, bh1);
                }
            }
        }
        __syncthreads();
    }

#pragma unroll
    for (int mt = 0; mt < 2; mt++) {
#pragma unroll
        for (int nt = 0; nt < 8; nt++) {
            const int r0 = bm + wm * 32 + mt * 16 + (lane >> 2);
            const int cn = bn + wn * 64 + nt * 8 + (lane & 3) * 2;
            if (scatter) {
                const int head = cn >> 6, d = cn & 63;
#pragma unroll
                for (int half = 0; half < 2; half++) {
                    const int rm = r0 + half * 8;
                    const int b = rm >> 11, s = rm & 2047;
                    float* dst = C + (((size_t)(b * heads + head)) * S_LEN + s) * HD + d;
                    *(float2*)dst = make_float2(acc[mt][nt][half * 2], acc[mt][nt][half * 2 + 1]);
                }
            } else {
                *(float2*)(C + (size_t)r0 * N + cn) =
                    make_float2(acc[mt][nt][0], acc[mt][nt][1]);
                *(float2*)(C + (size_t)(r0 + 8) * N + cn) =
                    make_float2(acc[mt][nt][2], acc[mt][nt][3]);
            }
        }
    }
}

// ---------------- fp32 -> bf16 hi/lo split ----------------
__global__ __launch_bounds__(256) void split_kernel(
    const float* __restrict__ X, __nv_bfloat16* __restrict__ Hi,
    __nv_bfloat16* __restrict__ Lo, int n4)
{
    const int i = blockIdx.x * 256 + threadIdx.x;
    if (i >= n4) return;
    const float4 v = ((const float4*)X)[i];
    float x[4] = {v.x, v.y, v.z, v.w};
    __nv_bfloat16 h[4], l[4];
#pragma unroll
    for (int e = 0; e < 4; e++) {
        h[e] = __float2bfloat16(x[e]);
        l[e] = __float2bfloat16(x[e] - __bfloat162float(h[e]));
    }
    ((__nv_bfloat162*)Hi)[2 * i]     = __nv_bfloat162(h[0], h[1]);
    ((__nv_bfloat162*)Hi)[2 * i + 1] = __nv_bfloat162(h[2], h[3]);
    ((__nv_bfloat162*)Lo)[2 * i]     = __nv_bfloat162(l[0], l[1]);
    ((__nv_bfloat162*)Lo)[2 * i + 1] = __nv_bfloat162(l[2], l[3]);
}

// ---------------- W[K,N] fp32 -> Wt[N,K] bf16 hi/lo ----------------
__global__ __launch_bounds__(256) void transpose_split_kernel(
    const float* __restrict__ W, __nv_bfloat16* __restrict__ Thi,
    __nv_bfloat16* __restrict__ Tlo, int K, int N)
{
    __shared__ float t[32][33];
    const int k0 = blockIdx.y * 32, n0 = blockIdx.x * 32;
    const int tx = threadIdx.x, ty = threadIdx.y;
#pragma unroll
    for (int i = 0; i < 32; i += 8)
        t[ty + i][tx] = W[(size_t)(k0 + ty + i) * N + n0 + tx];
    __syncthreads();
#pragma unroll
    for (int i = 0; i < 32; i += 8) {
        const float x = t[tx][ty + i];
        const __nv_bfloat16 h = __float2bfloat16(x);
        const __nv_bfloat16 l = __float2bfloat16(x - __bfloat162float(h));
        Thi[(size_t)(n0 + ty + i) * K + k0 + tx] = h;
        Tlo[(size_t)(n0 + ty + i) * K + k0 + tx] = l;
    }
}

// ---------------- V [bk,s,d] fp32 -> Vt [bk,d,s] bf16 hi/lo ----------------
__global__ __launch_bounds__(256) void vtrans_split_kernel(
    const float* __restrict__ V, __nv_bfloat16* __restrict__ Thi,
    __nv_bfloat16* __restrict__ Tlo)
{
    __shared__ float t[32][33];
    const int s0 = blockIdx.x << 5, d0 = blockIdx.y << 5;
    const int bk = blockIdx.z;
    const int tx = threadIdx.x, ty = threadIdx.y;
    const float* src = V + (size_t)bk * S_LEN * HD;
#pragma unroll
    for (int i = 0; i < 32; i += 8)
        t[ty + i][tx] = src[(size_t)(s0 + ty + i) * HD + d0 + tx];
    __syncthreads();
    __nv_bfloat16* dh = Thi + (size_t)bk * HD * S_LEN;
    __nv_bfloat16* dl = Tlo + (size_t)bk * HD * S_LEN;
#pragma unroll
    for (int i = 0; i < 32; i += 8) {
        const float x = t[tx][ty + i];
        const __nv_bfloat16 h = __float2bfloat16(x);
        const __nv_bfloat16 l = __float2bfloat16(x - __bfloat162float(h));
        dh[(size_t)(d0 + ty + i) * S_LEN + s0 + tx] = h;
        dl[(size_t)(d0 + ty + i) * S_LEN + s0 + tx] = l;
    }
}

// ---------------- RMSNorm + RoPE, output split bf16 hi/lo ----------------
__global__ __launch_bounds__(256) void norm_rope_split_kernel(
    const float* __restrict__ X, const float* __restrict__ w,
    const float* __restrict__ cosb, const float* __restrict__ sinb,
    __nv_bfloat16* __restrict__ Hi, __nv_bfloat16* __restrict__ Lo, int rows)
{
    const int row = blockIdx.x * 8 + threadIdx.y;
    if (row >= rows) return;
    const int lane = threadIdx.x;
    const int s = row & (S_LEN - 1);

    float2 x = *(const float2*)(X + (size_t)row * HD + lane * 2);
    float ssq = x.x * x.x + x.y * x.y;
#pragma unroll
    for (int m = 16; m; m >>= 1) ssq += __shfl_xor_sync(0xffffffffu, ssq, m);
    const float inv = rsqrtf(ssq * (1.0f / 64.0f) + 1e-6f);

    const float n0 = x.x * inv * w[lane * 2];
    const float n1 = x.y * inv * w[lane * 2 + 1];
    const float c0 = cosb[(size_t)s * HD + lane * 2];
    const float c1 = cosb[(size_t)s * HD + lane * 2 + 1];
    const float s0 = sinb[(size_t)s * HD + lane * 2];
    const float s1 = sinb[(size_t)s * HD + lane * 2 + 1];

    const float ox = n0 * c0 - n1 * s0;
    const float oy = n1 * c1 + n0 * s1;

    const __nv_bfloat16 hx = __float2bfloat16(ox);
    const __nv_bfloat16 hy = __float2bfloat16(oy);
    const __nv_bfloat16 lx = __float2bfloat16(ox - __bfloat162float(hx));
    const __nv_bfloat16 ly = __float2bfloat16(oy - __bfloat162float(hy));
    *(__nv_bfloat162*)(Hi + (size_t)row * HD + lane * 2) = __nv_bfloat162(hx, hy);
    *(__nv_bfloat162*)(Lo + (size_t)row * HD + lane * 2) = __nv_bfloat162(lx, ly);
}

// ---------------- flash attention via bf16 mma (causal, GQA) --------------
// Br=128 rows/block, Bc=64, 8 warps; warp w owns rows 16w..16w+15.
#define FSTR 72
#define FLASH_SMEM ((128 * FSTR * 2 + 64 * FSTR * 2 + 64 * FSTR * 2) * 2) /* bytes = 73728 */

__global__ __launch_bounds__(256) void flash_mma_kernel(
    const __nv_bfloat16* __restrict__ Qhi, const __nv_bfloat16* __restrict__ Qlo,
    const __nv_bfloat16* __restrict__ Khi, const __nv_bfloat16* __restrict__ Klo,
    const __nv_bfloat16* __restrict__ Vhi, const __nv_bfloat16* __restrict__ Vlo,
    float* __restrict__ O)
{
    extern __shared__ __nv_bfloat16 sm[];
    __nv_bfloat16* sQh = sm;
    __nv_bfloat16* sQl = sQh + 128 * FSTR;
    __nv_bfloat16* sKh = sQl + 128 * FSTR;
    __nv_bfloat16* sKl = sKh + 64 * FSTR;
    __nv_bfloat16* sVh = sKl + 64 * FSTR;
    __nv_bfloat16* sVl = sVh + 64 * FSTR;

    const int tid = threadIdx.x, lane = tid & 31, wid = tid >> 5;
    const int ib = (int)gridDim.x - 1 - (int)blockIdx.x;   // heavy blocks first
    const int bh = blockIdx.y;
    const int b = bh >> 4, h = bh & 15, kvh = (bh & 15) >> 2;
    const int i0 = ib << 7;

    const __nv_bfloat16* Qhb = Qhi + ((size_t)(b * NHQ + h) * S_LEN + i0) * HD;
    const __nv_bfloat16* Qlb = Qlo + ((size_t)(b * NHQ + h) * S_LEN + i0) * HD;
    const __nv_bfloat16* Khb = Khi + (size_t)(b * NKV + kvh) * S_LEN * HD;
    const __nv_bfloat16* Klb = Klo + (size_t)(b * NKV + kvh) * S_LEN * HD;
    const __nv_bfloat16* Vhb = Vhi + (size_t)(b * NKV + kvh) * HD * S_LEN;
    const __nv_bfloat16* Vlb = Vlo + (size_t)(b * NKV + kvh) * HD * S_LEN;

    // load Q tile (128 x 64, hi/lo)
    for (int it = tid; it < 1024; it += 256) {
        const int r = it >> 3, j = (it & 7) << 3;
        *(uint4*)&sQh[r * FSTR + j] = *(const uint4*)(Qhb + (size_t)r * HD + j);
        *(uint4*)&sQl[r * FSTR + j] = *(const uint4*)(Qlb + (size_t)r * HD + j);
    }

    const int lr = lane >> 2, lc = (lane & 3) << 1;
    const int gr = i0 + (wid << 4) + lr;     // this thread's row (and gr+8)

    float m0 = -1e30f, m1 = -1e30f, l0 = 0.f, l1 = 0.f;
    float o[8][4];
#pragma unroll
    for (int nt = 0; nt < 8; nt++)
#pragma unroll
        for (int e = 0; e < 4; e++) o[nt][e] = 0.f;

    const float K2 = 0.1803368801f;   // 0.125 * log2(e)
    const int ntiles = 2 * ib + 2;

    for (int t = 0; t < ntiles; t++) {
        const int j0 = t << 6;
        __syncthreads();
        for (int it = tid; it < 512; it += 256) {
            const int r = it >> 3, j = (it & 7) << 3;
            *(uint4*)&sKh[r * FSTR + j] = *(const uint4*)(Khb + (size_t)(j0 + r) * HD + j);
            *(uint4*)&sKl[r * FSTR + j] = *(const uint4*)(Klb + (size_t)(j0 + r) * HD + j);
            *(uint4*)&sVh[r * FSTR + j] = *(const uint4*)(Vhb + (size_t)r * S_LEN + j0 + j);
            *(uint4*)&sVl[r * FSTR + j] = *(const uint4*)(Vlb + (size_t)r * S_LEN + j0 + j);
        }
        __syncthreads();

        // ---- S = Q K^T (3-term bf16) ----
        float s[8][4];
#pragma unroll
        for (int nt = 0; nt < 8; nt++)
#pragma unroll
            for (int e = 0; e < 4; e++) s[nt][e] = 0.f;

#pragma unroll
        for (int ks = 0; ks < 4; ks++) {
            const int ar = (wid << 4) + lr;
            const int ac = (ks << 4) + lc;
            uint32_t qh[4], ql[4];
            qh[0] = *(const uint32_t*)&sQh[ar * FSTR + ac];
            qh[1] = *(const uint32_t*)&sQh[(ar + 8) * FSTR + ac];
            qh[2] = *(const uint32_t*)&sQh[ar * FSTR + ac + 8];
            qh[3] = *(const uint32_t*)&sQh[(ar + 8) * FSTR + ac + 8];
            ql[0] = *(const uint32_t*)&sQl[ar * FSTR + ac];
            ql[1] = *(const uint32_t*)&sQl[(ar + 8) * FSTR + ac];
            ql[2] = *(const uint32_t*)&sQl[ar * FSTR + ac + 8];
            ql[3] = *(const uint32_t*)&sQl[(ar + 8) * FSTR + ac + 8];
#pragma unroll
            for (int nt = 0; nt < 8; nt++) {
                const int kr = (nt << 3) + lr;
                const uint32_t kh0 = *(const uint32_t*)&sKh[kr * FSTR + ac];
                const uint32_t kh1 = *(const uint32_t*)&sKh[kr * FSTR + ac + 8];
                const uint32_t kl0 = *(const uint32_t*)&sKl[kr * FSTR + ac];
                const uint32_t kl1 = *(const uint32_t*)&sKl[kr * FSTR + ac + 8];
                mma_bf16(s[nt], qh, kl0, kl1);
                mma_bf16(s[nt], ql, kh0, kh1);
                mma_bf16(s[nt], qh, kh0, kh1);
            }
        }

        // ---- scale to base-2, causal mask ----
        if (j0 + 64 > i0 + (wid << 4)) {
#pragma unroll
            for (int nt = 0; nt < 8; nt++) {
                const int col = j0 + (nt << 3) + lc;
                s[nt][0] = (col     > gr    ) ? -1e30f : s[nt][0] * K2;
                s[nt][1] = (col + 1 > gr    ) ? -1e30f : s[nt][1] * K2;
                s[nt][2] = (col     > gr + 8) ? -1e30f : s[nt][2] * K2;
                s[nt][3] = (col + 1 > gr + 8) ? -1e30f : s[nt][3] * K2;
            }
        } else {
#pragma unroll
            for (int nt = 0; nt < 8; nt++)
#pragma unroll
                for (int e = 0; e < 4; e++) s[nt][e] *= K2;
        }

        // ---- online softmax (base-2 domain, FMA-pipe exp) ----
        float rm0 = -1e30f, rm1 = -1e30f;
#pragma unroll
        for (int nt = 0; nt < 8; nt++) {
            rm0 = fmaxf(rm0, fmaxf(s[nt][0], s[nt][1]));
            rm1 = fmaxf(rm1, fmaxf(s[nt][2], s[nt][3]));
        }
        rm0 = fmaxf(rm0, __shfl_xor_sync(0xffffffffu, rm0, 1));
        rm0 = fmaxf(rm0, __shfl_xor_sync(0xffffffffu, rm0, 2));
        rm1 = fmaxf(rm1, __shfl_xor_sync(0xffffffffu, rm1, 1));
        rm1 = fmaxf(rm1, __shfl_xor_sync(0xffffffffu, rm1, 2));
        const float m0n = fmaxf(m0, rm0), m1n = fmaxf(m1, rm1);
        const float c0 = exp2p(m0 - m0n), c1 = exp2p(m1 - m1n);
        m0 = m0n; m1 = m1n;

        float rs0 = 0.f, rs1 = 0.f;
#pragma unroll
        for (int nt = 0; nt < 8; nt++) {
            s[nt][0] = exp2p(s[nt][0] - m0); rs0 += s[nt][0];
            s[nt][1] = exp2p(s[nt][1] - m0); rs0 += s[nt][1];
            s[nt][2] = exp2p(s[nt][2] - m1); rs1 += s[nt][2];
            s[nt][3] = exp2p(s[nt][3] - m1); rs1 += s[nt][3];
        }
        rs0 += __shfl_xor_sync(0xffffffffu, rs0, 1);
        rs0 += __shfl_xor_sync(0xffffffffu, rs0, 2);
        rs1 += __shfl_xor_sync(0xffffffffu, rs1, 1);
        rs1 += __shfl_xor_sync(0xffffffffu, rs1, 2);
        l0 = l0 * c0 + rs0;
        l1 = l1 * c1 + rs1;
#pragma unroll
        for (int nt = 0; nt < 8; nt++) {
            o[nt][0] *= c0; o[nt][1] *= c0;
            o[nt][2] *= c1; o[nt][3] *= c1;
        }

        // ---- O += P V (P stays in registers; 3-term bf16) ----
#pragma unroll
        for (int ks = 0; ks < 4; ks++) {
            uint32_t ph[4], pl[4];
            ph[0] = packbf(s[2 * ks][0],     s[2 * ks][1]);
            ph[1] = packbf(s[2 * ks][2],     s[2 * ks][3]);
            ph[2] = packbf(s[2 * ks + 1][0], s[2 * ks + 1][1]);
            ph[3] = packbf(s[2 * ks + 1][2], s[2 * ks + 1][3]);
#pragma unroll
            for (int e = 0; e < 4; e++) {
                const float* sv = s[2 * ks + (e >> 1)];
                const int base = (e & 1) << 1;
                const float f0 = sv[base]     - __uint_as_float(ph[e] << 16);
                const float f1 = sv[base + 1] - __uint_as_float(ph[e] & 0xFFFF0000u);
                pl[e] = packbf(f0, f1);
            }
            const int vc = (ks << 4) + lc;
#pragma unroll
            for (int nt = 0; nt < 8; nt++) {
                const int vr = (nt << 3) + lr;
                const uint32_t vh0 = *(const uint32_t*)&sVh[vr * FSTR + vc];
                const uint32_t vh1 = *(const uint32_t*)&sVh[vr * FSTR + vc + 8];
                const uint32_t vl0 = *(const uint32_t*)&sVl[vr * FSTR + vc];
                const uint32_t vl1 = *(const uint32_t*)&sVl[vr * FSTR + vc + 8];
                mma_bf16(o[nt], ph, vl0, vl1);
                mma_bf16(o[nt], pl, vh0, vh1);
                mma_bf16(o[nt], ph, vh0, vh1);
            }
        }
    }

    // ---- finalize + write [b, s, h*HD] ----
    const float inv0 = 1.f / l0, inv1 = 1.f / l1;
#pragma unroll
    for (int nt = 0; nt < 8; nt++) {
        const int d = (nt << 3) + lc;
        float* dst0 = O + ((size_t)b * S_LEN + gr) * (NHQ * HD) + h * HD + d;
        float* dst1 = O + ((size_t)b * S_LEN + gr + 8) * (NHQ * HD) + h * HD + d;
        *(float2*)dst0 = make_float2(o[nt][0] * inv0, o[nt][1] * inv0);
        *(float2*)dst1 = make_float2(o[nt][2] * inv1, o[nt][3] * inv1);
    }
}

// ---------------- launch ----------------
extern "C" void kernel_launch(void* const* d_in, const int* in_sizes, int n_in,
                              void* d_out, int out_size)
{
    const float* X    = (const float*)d_in[0];
    const float* cosb = (const float*)d_in[2];
    const float* sinb = (const float*)d_in[3];
    const float* Wq   = (const float*)d_in[4];
    const float* Wk   = (const float*)d_in[5];
    const float* Wv   = (const float*)d_in[6];
    const float* Wo   = (const float*)d_in[7];
    const float* qw   = (const float*)d_in[8];
    const float* kw   = (const float*)d_in[9];
    float* out = (float*)d_out;

    void *pQ, *pK, *pV, *pA;
    void *pXhi, *pXlo, *pAhi, *pAlo, *pKhi, *pKlo, *pVthi, *pVtlo;
    void *pWq_h, *pWq_l, *pWk_h, *pWk_l, *pWv_h, *pWv_l, *pWo_h, *pWo_l;
    cudaGetSymbolAddress(&pQ, g_Q);
    cudaGetSymbolAddress(&pK, g_K);
    cudaGetSymbolAddress(&pV, g_V);
    cudaGetSymbolAddress(&pA, g_attn);
    cudaGetSymbolAddress(&pXhi, g_Xhi);
    cudaGetSymbolAddress(&pXlo, g_Xlo);
    cudaGetSymbolAddress(&pAhi, g_Ahi);
    cudaGetSymbolAddress(&pAlo, g_Alo);
    cudaGetSymbolAddress(&pKhi, g_Khi);
    cudaGetSymbolAddress(&pKlo, g_Klo);
    cudaGetSymbolAddress(&pVthi, g_Vthi);
    cudaGetSymbolAddress(&pVtlo, g_Vtlo);
    cudaGetSymbolAddress(&pWq_h, g_Wqt_hi);
    cudaGetSymbolAddress(&pWq_l, g_Wqt_lo);
    cudaGetSymbolAddress(&pWk_h, g_Wkt_hi);
    cudaGetSymbolAddress(&pWk_l, g_Wkt_lo);
    cudaGetSymbolAddress(&pWv_h, g_Wvt_hi);
    cudaGetSymbolAddress(&pWv_l, g_Wvt_lo);
    cudaGetSymbolAddress(&pWo_h, g_Wot_hi);
    cudaGetSymbolAddress(&pWo_l, g_Wot_lo);

    cudaFuncSetAttribute(flash_mma_kernel, cudaFuncAttributeMaxDynamicSharedMemorySize, FLASH_SMEM);

    const int M = BATCH * S_LEN;          // 8192
    const int n4 = M * HDIM / 4;

    // input splits / weight transposes
    split_kernel<<<(n4 + 255) / 256, 256>>>(X, (__nv_bfloat16*)pXhi, (__nv_bfloat16*)pXlo, n4);
    transpose_split_kernel<<<dim3(HDIM / 32, HDIM / 32), dim3(32, 8)>>>(Wq, (__nv_bfloat16*)pWq_h, (__nv_bfloat16*)pWq_l, HDIM, HDIM);
    transpose_split_kernel<<<dim3(256 / 32, HDIM / 32), dim3(32, 8)>>>(Wk, (__nv_bfloat16*)pWk_h, (__nv_bfloat16*)pWk_l, HDIM, 256);
    transpose_split_kernel<<<dim3(256 / 32, HDIM / 32), dim3(32, 8)>>>(Wv, (__nv_bfloat16*)pWv_h, (__nv_bfloat16*)pWv_l, HDIM, 256);
    transpose_split_kernel<<<dim3(HDIM / 32, HDIM / 32), dim3(32, 8)>>>(Wo, (__nv_bfloat16*)pWo_h, (__nv_bfloat16*)pWo_l, HDIM, HDIM);

    // QKV projections
    gemm_bf16_kernel<<<dim3(NHQ * HD / 128, M / 128), 256>>>(
        (const __nv_bfloat16*)pXhi, (const __nv_bfloat16*)pXlo,
        (const __nv_bfloat16*)pWq_h, (const __nv_bfloat16*)pWq_l,
        (float*)pQ, NHQ * HD, 1, NHQ);
    gemm_bf16_kernel<<<dim3(NKV * HD / 128, M / 128), 256>>>(
        (const __nv_bfloat16*)pXhi, (const __nv_bfloat16*)pXlo,
        (const __nv_bfloat16*)pWk_h, (const __nv_bfloat16*)pWk_l,
        (float*)pK, NKV * HD, 1, NKV);
    gemm_bf16_kernel<<<dim3(NKV * HD / 128, M / 128), 256>>>(
        (const __nv_bfloat16*)pXhi, (const __nv_bfloat16*)pXlo,
        (const __nv_bfloat16*)pWv_h, (const __nv_bfloat16*)pWv_l,
        (float*)pV, NKV * HD, 1, NKV);

    // RMSNorm + RoPE with fused bf16 hi/lo split
    norm_rope_split_kernel<<<(BATCH * NHQ * S_LEN) / 8, dim3(32, 8)>>>(
        (const float*)pQ, qw, cosb, sinb,
        (__nv_bfloat16*)pAhi, (__nv_bfloat16*)pAlo, BATCH * NHQ * S_LEN);
    norm_rope_split_kernel<<<(BATCH * NKV * S_LEN) / 8, dim3(32, 8)>>>(
        (const float*)pK, kw, cosb, sinb,
        (__nv_bfloat16*)pKhi, (__nv_bfloat16*)pKlo, BATCH * NKV * S_LEN);

    // V transpose + split
    vtrans_split_kernel<<<dim3(S_LEN / 32, HD / 32, BATCH * NKV), dim3(32, 8)>>>(
        (const float*)pV, (__nv_bfloat16*)pVthi, (__nv_bfloat16*)pVtlo);

    // flash attention (tensor-pipe)
    flash_mma_kernel<<<dim3(S_LEN / 128, BATCH * NHQ), 256, FLASH_SMEM>>>(
        (const __nv_bfloat16*)pAhi, (const __nv_bfloat16*)pAlo,
        (const __nv_bfloat16*)pKhi, (const __nv_bfloat16*)pKlo,
        (const __nv_bfloat16*)pVthi, (const __nv_bfloat16*)pVtlo,
        (float*)pA);

    // split attn (reuse Q split buffers), O-projection
    split_kernel<<<(n4 + 255) / 256, 256>>>((const float*)pA, (__nv_bfloat16*)pAhi, (__nv_bfloat16*)pAlo, n4);
    gemm_bf16_kernel<<<dim3(HDIM / 128, M / 128), 256>>>(
        (const __nv_bfloat16*)pAhi, (const __nv_bfloat16*)pAlo,
        (const __nv_bfloat16*)pWo_h, (const __nv_bfloat16*)pWo_l,
        out, HDIM, 0, 0);
}

// round 16
// speedup vs baseline: 1.9512x; 1.0831x over previous
#include <cuda_runtime.h>
#include <cuda_bf16.h>
#include <cstdint>

#define BATCH 4
#define S_LEN 2048
#define HDIM  1024
#define NHQ   16
#define NKV   4
#define HD    64

// ---------------- device scratch (no cudaMalloc allowed) ----------------
__device__ float g_Q[(size_t)BATCH * NHQ * S_LEN * HD];    // [b, h, s, d]
__device__ float g_K[(size_t)BATCH * NKV * S_LEN * HD];    // [b, kvh, s, d]
__device__ float g_V[(size_t)BATCH * NKV * S_LEN * HD];    // [b, kvh, s, d]
__device__ float g_attn[(size_t)BATCH * S_LEN * NHQ * HD]; // [b, s, h*HD]

__device__ __align__(16) __nv_bfloat16 g_Xhi[(size_t)BATCH * S_LEN * HDIM];
__device__ __align__(16) __nv_bfloat16 g_Xlo[(size_t)BATCH * S_LEN * HDIM];
__device__ __align__(16) __nv_bfloat16 g_Ahi[(size_t)BATCH * S_LEN * HDIM];  // Qhi, later attn-hi
__device__ __align__(16) __nv_bfloat16 g_Alo[(size_t)BATCH * S_LEN * HDIM];  // Qlo, later attn-lo
__device__ __align__(16) __nv_bfloat16 g_Khi[(size_t)BATCH * NKV * S_LEN * HD];
__device__ __align__(16) __nv_bfloat16 g_Klo[(size_t)BATCH * NKV * S_LEN * HD];
__device__ __align__(16) __nv_bfloat16 g_Vthi[(size_t)BATCH * NKV * HD * S_LEN]; // [b,kvh,d,s]
__device__ __align__(16) __nv_bfloat16 g_Vtlo[(size_t)BATCH * NKV * HD * S_LEN];
__device__ __align__(16) __nv_bfloat16 g_Wqt_hi[(size_t)HDIM * HDIM];
__device__ __align__(16) __nv_bfloat16 g_Wqt_lo[(size_t)HDIM * HDIM];
__device__ __align__(16) __nv_bfloat16 g_Wkt_hi[(size_t)256 * HDIM];
__device__ __align__(16) __nv_bfloat16 g_Wkt_lo[(size_t)256 * HDIM];
__device__ __align__(16) __nv_bfloat16 g_Wvt_hi[(size_t)256 * HDIM];
__device__ __align__(16) __nv_bfloat16 g_Wvt_lo[(size_t)256 * HDIM];
__device__ __align__(16) __nv_bfloat16 g_Wot_hi[(size_t)HDIM * HDIM];
__device__ __align__(16) __nv_bfloat16 g_Wot_lo[(size_t)HDIM * HDIM];

// ---------------- helpers ----------------
__device__ __forceinline__ uint32_t s2u(const void* p) {
    uint32_t a;
    asm("{ .reg .u64 t; cvta.to.shared.u64 t, %1; cvt.u32.u64 %0, t; }"
        : "=r"(a) : "l"(p));
    return a;
}
__device__ __forceinline__ void ldsm_x4(uint32_t r[4], uint32_t saddr) {
    asm volatile("ldmatrix.sync.aligned.m8n8.x4.shared.b16 {%0,%1,%2,%3}, [%4];"
        : "=r"(r[0]), "=r"(r[1]), "=r"(r[2]), "=r"(r[3]) : "r"(saddr));
}
__device__ __forceinline__ void mma_bf16(float c[4], const uint32_t a[4],
                                         uint32_t b0, uint32_t b1) {
    asm volatile(
        "mma.sync.aligned.m16n8k16.row.col.f32.bf16.bf16.f32 "
        "{%0,%1,%2,%3},{%4,%5,%6,%7},{%8,%9},{%0,%1,%2,%3};"
        : "+f"(c[0]), "+f"(c[1]), "+f"(c[2]), "+f"(c[3])
        : "r"(a[0]), "r"(a[1]), "r"(a[2]), "r"(a[3]), "r"(b0), "r"(b1));
}
__device__ __forceinline__ uint32_t packbf(float lo, float hi) {
    uint32_t r;
    asm("cvt.rn.bf16x2.f32 %0, %1, %2;" : "=r"(r) : "f"(hi), "f"(lo));
    return r;
}
// 2^x on the FMA pipe, x <= 0 expected; rel err ~1e-4
__device__ __forceinline__ float exp2p(float x) {
    x = fmaxf(x, -126.f);
    const float n = floorf(x);
    const float f = x - n;
    float p = 1.33335581e-3f;
    p = fmaf(p, f, 9.61812910e-3f);
    p = fmaf(p, f, 5.55041087e-2f);
    p = fmaf(p, f, 2.40226507e-1f);
    p = fmaf(p, f, 6.93147182e-1f);
    p = fmaf(p, f, 1.0f);
    return p * __int_as_float(((int)n + 127) << 23);
}

// ---------------- 128x128 GEMM, 3-term bf16, K=1024, ldmatrix frags -------
#define SSTR 40

__global__ __launch_bounds__(256) void gemm_bf16_kernel(
    const __nv_bfloat16* __restrict__ Ahi, const __nv_bfloat16* __restrict__ Alo,
    const __nv_bfloat16* __restrict__ Bhi, const __nv_bfloat16* __restrict__ Blo,
    float* __restrict__ C, int N, int scatter, int heads)
{
    __shared__ __nv_bfloat16 sAh[128][SSTR], sAl[128][SSTR];
    __shared__ __nv_bfloat16 sBh[128][SSTR], sBl[128][SSTR];

    const int tid = threadIdx.x;
    const int lane = tid & 31, warp = tid >> 5;
    const int wm = warp & 3;
    const int wn = warp >> 2;
    const int bm = blockIdx.y << 7;
    const int bn = blockIdx.x << 7;

    const int sr = tid >> 1;
    const int sc = (tid & 1) << 4;

    // ldmatrix lane addresses (byte offsets into smem)
    const uint32_t aRow = wm * 32 + (lane & 15);
    const uint32_t aColH = (lane >> 4) << 3;
    const uint32_t uAh = s2u(sAh) + (aRow * SSTR + aColH) * 2;
    const uint32_t uAl = s2u(sAl) + (aRow * SSTR + aColH) * 2;
    const uint32_t bRow = wn * 64 + (lane & 7) + (((lane >> 4) & 1) << 3);
    const uint32_t bColH = ((lane >> 3) & 1) << 3;
    const uint32_t uBh = s2u(sBh) + (bRow * SSTR + bColH) * 2;
    const uint32_t uBl = s2u(sBl) + (bRow * SSTR + bColH) * 2;

    float acc[2][8][4];
#pragma unroll
    for (int mt = 0; mt < 2; mt++)
#pragma unroll
        for (int nt = 0; nt < 8; nt++)
#pragma unroll
            for (int e = 0; e < 4; e++) acc[mt][nt][e] = 0.f;

    const size_t aoff = (size_t)(bm + sr) * HDIM + sc;
    const size_t boff = (size_t)(bn + sr) * HDIM + sc;

    uint4 pAh[2], pAl[2], pBh[2], pBl[2];
    pAh[0] = *(const uint4*)(Ahi + aoff); pAh[1] = *(const uint4*)(Ahi + aoff + 8);
    pAl[0] = *(const uint4*)(Alo + aoff); pAl[1] = *(const uint4*)(Alo + aoff + 8);
    pBh[0] = *(const uint4*)(Bhi + boff); pBh[1] = *(const uint4*)(Bhi + boff + 8);
    pBl[0] = *(const uint4*)(Blo + boff); pBl[1] = *(const uint4*)(Blo + boff + 8);

    for (int k0 = 0; k0 < HDIM; k0 += 32) {
        *(uint4*)(&sAh[sr][sc]) = pAh[0]; *(uint4*)(&sAh[sr][sc + 8]) = pAh[1];
        *(uint4*)(&sAl[sr][sc]) = pAl[0]; *(uint4*)(&sAl[sr][sc + 8]) = pAl[1];
        *(uint4*)(&sBh[sr][sc]) = pBh[0]; *(uint4*)(&sBh[sr][sc + 8]) = pBh[1];
        *(uint4*)(&sBl[sr][sc]) = pBl[0]; *(uint4*)(&sBl[sr][sc + 8]) = pBl[1];
        __syncthreads();

        if (k0 + 32 < HDIM) {
            const size_t na = aoff + k0 + 32, nb = boff + k0 + 32;
            pAh[0] = *(const uint4*)(Ahi + na); pAh[1] = *(const uint4*)(Ahi + na + 8);
            pAl[0] = *(const uint4*)(Alo + na); pAl[1] = *(const uint4*)(Alo + na + 8);
            pBh[0] = *(const uint4*)(Bhi + nb); pBh[1] = *(const uint4*)(Bhi + nb + 8);
            pBl[0] = *(const uint4*)(Blo + nb); pBl[1] = *(const uint4*)(Blo + nb + 8);
        }

#pragma unroll
        for (int ks = 0; ks < 2; ks++) {
            const uint32_t kb = ks * 32;   // 16 halfwords = 32 bytes
            uint32_t ah[2][4], al[2][4];
            ldsm_x4(ah[0], uAh + kb); ldsm_x4(ah[1], uAh + 16 * SSTR * 2 + kb);
            ldsm_x4(al[0], uAl + kb); ldsm_x4(al[1], uAl + 16 * SSTR * 2 + kb);
#pragma unroll
            for (int p = 0; p < 4; p++) {
                uint32_t bh[4], bl[4];
                ldsm_x4(bh, uBh + p * (16 * SSTR * 2) + kb);
                ldsm_x4(bl, uBl + p * (16 * SSTR * 2) + kb);
#pragma unroll
                for (int mt = 0; mt < 2; mt++) {
                    mma_bf16(acc[mt][2 * p],     ah[mt], bl[0], bl[1]);
                    mma_bf16(acc[mt][2 * p],     al[mt], bh[0], bh[1]);
                    mma_bf16(acc[mt][2 * p],     ah[mt], bh[0], bh[1]);
                    mma_bf16(acc[mt][2 * p + 1], ah[mt], bl[2], bl[3]);
                    mma_bf16(acc[mt][2 * p + 1], al[mt], bh[2], bh[3]);
                    mma_bf16(acc[mt][2 * p + 1], ah[mt], bh[2], bh[3]);
                }
            }
        }
        __syncthreads();
    }

#pragma unroll
    for (int mt = 0; mt < 2; mt++) {
#pragma unroll
        for (int nt = 0; nt < 8; nt++) {
            const int r0 = bm + wm * 32 + mt * 16 + (lane >> 2);
            const int cn = bn + wn * 64 + nt * 8 + (lane & 3) * 2;
            if (scatter) {
                const int head = cn >> 6, d = cn & 63;
#pragma unroll
                for (int half = 0; half < 2; half++) {
                    const int rm = r0 + half * 8;
                    const int b = rm >> 11, s = rm & 2047;
                    float* dst = C + (((size_t)(b * heads + head)) * S_LEN + s) * HD + d;
                    *(float2*)dst = make_float2(acc[mt][nt][half * 2], acc[mt][nt][half * 2 + 1]);
                }
            } else {
                *(float2*)(C + (size_t)r0 * N + cn) =
                    make_float2(acc[mt][nt][0], acc[mt][nt][1]);
                *(float2*)(C + (size_t)(r0 + 8) * N + cn) =
                    make_float2(acc[mt][nt][2], acc[mt][nt][3]);
            }
        }
    }
}

// ---------------- fp32 -> bf16 hi/lo split ----------------
__global__ __launch_bounds__(256) void split_kernel(
    const float* __restrict__ X, __nv_bfloat16* __restrict__ Hi,
    __nv_bfloat16* __restrict__ Lo, int n4)
{
    const int i = blockIdx.x * 256 + threadIdx.x;
    if (i >= n4) return;
    const float4 v = ((const float4*)X)[i];
    float x[4] = {v.x, v.y, v.z, v.w};
    __nv_bfloat16 h[4], l[4];
#pragma unroll
    for (int e = 0; e < 4; e++) {
        h[e] = __float2bfloat16(x[e]);
        l[e] = __float2bfloat16(x[e] - __bfloat162float(h[e]));
    }
    ((__nv_bfloat162*)Hi)[2 * i]     = __nv_bfloat162(h[0], h[1]);
    ((__nv_bfloat162*)Hi)[2 * i + 1] = __nv_bfloat162(h[2], h[3]);
    ((__nv_bfloat162*)Lo)[2 * i]     = __nv_bfloat162(l[0], l[1]);
    ((__nv_bfloat162*)Lo)[2 * i + 1] = __nv_bfloat162(l[2], l[3]);
}

// ---------------- W[K,N] fp32 -> Wt[N,K] bf16 hi/lo ----------------
__global__ __launch_bounds__(256) void transpose_split_kernel(
    const float* __restrict__ W, __nv_bfloat16* __restrict__ Thi,
    __nv_bfloat16* __restrict__ Tlo, int K, int N)
{
    __shared__ float t[32][33];
    const int k0 = blockIdx.y * 32, n0 = blockIdx.x * 32;
    const int tx = threadIdx.x, ty = threadIdx.y;
#pragma unroll
    for (int i = 0; i < 32; i += 8)
        t[ty + i][tx] = W[(size_t)(k0 + ty + i) * N + n0 + tx];
    __syncthreads();
#pragma unroll
    for (int i = 0; i < 32; i += 8) {
        const float x = t[tx][ty + i];
        const __nv_bfloat16 h = __float2bfloat16(x);
        const __nv_bfloat16 l = __float2bfloat16(x - __bfloat162float(h));
        Thi[(size_t)(n0 + ty + i) * K + k0 + tx] = h;
        Tlo[(size_t)(n0 + ty + i) * K + k0 + tx] = l;
    }
}

// ---------------- V [bk,s,d] fp32 -> Vt [bk,d,s] bf16 hi/lo ----------------
__global__ __launch_bounds__(256) void vtrans_split_kernel(
    const float* __restrict__ V, __nv_bfloat16* __restrict__ Thi,
    __nv_bfloat16* __restrict__ Tlo)
{
    __shared__ float t[32][33];
    const int s0 = blockIdx.x << 5, d0 = blockIdx.y << 5;
    const int bk = blockIdx.z;
    const int tx = threadIdx.x, ty = threadIdx.y;
    const float* src = V + (size_t)bk * S_LEN * HD;
#pragma unroll
    for (int i = 0; i < 32; i += 8)
        t[ty + i][tx] = src[(size_t)(s0 + ty + i) * HD + d0 + tx];
    __syncthreads();
    __nv_bfloat16* dh = Thi + (size_t)bk * HD * S_LEN;
    __nv_bfloat16* dl = Tlo + (size_t)bk * HD * S_LEN;
#pragma unroll
    for (int i = 0; i < 32; i += 8) {
        const float x = t[tx][ty + i];
        const __nv_bfloat16 h = __float2bfloat16(x);
        const __nv_bfloat16 l = __float2bfloat16(x - __bfloat162float(h));
        dh[(size_t)(d0 + ty + i) * S_LEN + s0 + tx] = h;
        dl[(size_t)(d0 + ty + i) * S_LEN + s0 + tx] = l;
    }
}

// ---------------- RMSNorm + RoPE, output split bf16 hi/lo ----------------
__global__ __launch_bounds__(256) void norm_rope_split_kernel(
    const float* __restrict__ X, const float* __restrict__ w,
    const float* __restrict__ cosb, const float* __restrict__ sinb,
    __nv_bfloat16* __restrict__ Hi, __nv_bfloat16* __restrict__ Lo, int rows)
{
    const int row = blockIdx.x * 8 + threadIdx.y;
    if (row >= rows) return;
    const int lane = threadIdx.x;
    const int s = row & (S_LEN - 1);

    float2 x = *(const float2*)(X + (size_t)row * HD + lane * 2);
    float ssq = x.x * x.x + x.y * x.y;
#pragma unroll
    for (int m = 16; m; m >>= 1) ssq += __shfl_xor_sync(0xffffffffu, ssq, m);
    const float inv = rsqrtf(ssq * (1.0f / 64.0f) + 1e-6f);

    const float n0 = x.x * inv * w[lane * 2];
    const float n1 = x.y * inv * w[lane * 2 + 1];
    const float c0 = cosb[(size_t)s * HD + lane * 2];
    const float c1 = cosb[(size_t)s * HD + lane * 2 + 1];
    const float s0 = sinb[(size_t)s * HD + lane * 2];
    const float s1 = sinb[(size_t)s * HD + lane * 2 + 1];

    const float ox = n0 * c0 - n1 * s0;
    const float oy = n1 * c1 + n0 * s1;

    const __nv_bfloat16 hx = __float2bfloat16(ox);
    const __nv_bfloat16 hy = __float2bfloat16(oy);
    const __nv_bfloat16 lx = __float2bfloat16(ox - __bfloat162float(hx));
    const __nv_bfloat16 ly = __float2bfloat16(oy - __bfloat162float(hy));
    *(__nv_bfloat162*)(Hi + (size_t)row * HD + lane * 2) = __nv_bfloat162(hx, hy);
    *(__nv_bfloat162*)(Lo + (size_t)row * HD + lane * 2) = __nv_bfloat162(lx, ly);
}

// ---------------- flash attention via bf16 mma (causal, GQA) --------------
#define FSTR 72
#define FLASH_SMEM ((128 * FSTR * 2 + 64 * FSTR * 2 + 64 * FSTR * 2) * 2) /* 73728 B */

__global__ __launch_bounds__(256) void flash_mma_kernel(
    const __nv_bfloat16* __restrict__ Qhi, const __nv_bfloat16* __restrict__ Qlo,
    const __nv_bfloat16* __restrict__ Khi, const __nv_bfloat16* __restrict__ Klo,
    const __nv_bfloat16* __restrict__ Vhi, const __nv_bfloat16* __restrict__ Vlo,
    float* __restrict__ O)
{
    extern __shared__ __nv_bfloat16 sm[];
    __nv_bfloat16* sQh = sm;
    __nv_bfloat16* sQl = sQh + 128 * FSTR;
    __nv_bfloat16* sKh = sQl + 128 * FSTR;
    __nv_bfloat16* sKl = sKh + 64 * FSTR;
    __nv_bfloat16* sVh = sKl + 64 * FSTR;
    __nv_bfloat16* sVl = sVh + 64 * FSTR;

    const int tid = threadIdx.x, lane = tid & 31, wid = tid >> 5;
    const int ib = (int)gridDim.x - 1 - (int)blockIdx.x;   // heavy blocks first
    const int bh = blockIdx.y;
    const int b = bh >> 4, h = bh & 15, kvh = (bh & 15) >> 2;
    const int i0 = ib << 7;

    const __nv_bfloat16* Qhb = Qhi + ((size_t)(b * NHQ + h) * S_LEN + i0) * HD;
    const __nv_bfloat16* Qlb = Qlo + ((size_t)(b * NHQ + h) * S_LEN + i0) * HD;
    const __nv_bfloat16* Khb = Khi + (size_t)(b * NKV + kvh) * S_LEN * HD;
    const __nv_bfloat16* Klb = Klo + (size_t)(b * NKV + kvh) * S_LEN * HD;
    const __nv_bfloat16* Vhb = Vhi + (size_t)(b * NKV + kvh) * HD * S_LEN;
    const __nv_bfloat16* Vlb = Vlo + (size_t)(b * NKV + kvh) * HD * S_LEN;

    // load Q tile (128 x 64, hi/lo)
    for (int it = tid; it < 1024; it += 256) {
        const int r = it >> 3, j = (it & 7) << 3;
        *(uint4*)&sQh[r * FSTR + j] = *(const uint4*)(Qhb + (size_t)r * HD + j);
        *(uint4*)&sQl[r * FSTR + j] = *(const uint4*)(Qlb + (size_t)r * HD + j);
    }

    const int lr = lane >> 2, lc = (lane & 3) << 1;
    const int gr = i0 + (wid << 4) + lr;

    // ldmatrix lane addresses
    const uint32_t qRow = (wid << 4) + (lane & 15);
    const uint32_t colH = (lane >> 4) << 3;
    const uint32_t uQh = s2u(sQh) + (qRow * FSTR + colH) * 2;
    const uint32_t uQl = s2u(sQl) + (qRow * FSTR + colH) * 2;
    const uint32_t bRow = (lane & 7) + (((lane >> 4) & 1) << 3);
    const uint32_t bColH = ((lane >> 3) & 1) << 3;
    const uint32_t uKh = s2u(sKh) + (bRow * FSTR + bColH) * 2;
    const uint32_t uKl = s2u(sKl) + (bRow * FSTR + bColH) * 2;
    const uint32_t uVh = s2u(sVh) + (bRow * FSTR + bColH) * 2;
    const uint32_t uVl = s2u(sVl) + (bRow * FSTR + bColH) * 2;

    float m0 = -1e30f, m1 = -1e30f, l0 = 0.f, l1 = 0.f;
    float o[8][4];
#pragma unroll
    for (int nt = 0; nt < 8; nt++)
#pragma unroll
        for (int e = 0; e < 4; e++) o[nt][e] = 0.f;

    const float K2 = 0.1803368801f;   // 0.125 * log2(e)
    const int ntiles = 2 * ib + 2;

    for (int t = 0; t < ntiles; t++) {
        const int j0 = t << 6;
        __syncthreads();
        for (int it = tid; it < 512; it += 256) {
            const int r = it >> 3, j = (it & 7) << 3;
            *(uint4*)&sKh[r * FSTR + j] = *(const uint4*)(Khb + (size_t)(j0 + r) * HD + j);
            *(uint4*)&sKl[r * FSTR + j] = *(const uint4*)(Klb + (size_t)(j0 + r) * HD + j);
            *(uint4*)&sVh[r * FSTR + j] = *(const uint4*)(Vhb + (size_t)r * S_LEN + j0 + j);
            *(uint4*)&sVl[r * FSTR + j] = *(const uint4*)(Vlb + (size_t)r * S_LEN + j0 + j);
        }
        __syncthreads();

        // ---- S = Q K^T (3-term bf16, ldmatrix frags) ----
        float s[8][4];
#pragma unroll
        for (int nt = 0; nt < 8; nt++)
#pragma unroll
            for (int e = 0; e < 4; e++) s[nt][e] = 0.f;

#pragma unroll
        for (int ks = 0; ks < 4; ks++) {
            const uint32_t kb = ks * 32;
            uint32_t qh[4], ql[4];
            ldsm_x4(qh, uQh + kb);
            ldsm_x4(ql, uQl + kb);
#pragma unroll
            for (int p = 0; p < 4; p++) {
                uint32_t kh[4], kl[4];
                ldsm_x4(kh, uKh + p * (16 * FSTR * 2) + kb);
                ldsm_x4(kl, uKl + p * (16 * FSTR * 2) + kb);
                mma_bf16(s[2 * p],     qh, kl[0], kl[1]);
                mma_bf16(s[2 * p],     ql, kh[0], kh[1]);
                mma_bf16(s[2 * p],     qh, kh[0], kh[1]);
                mma_bf16(s[2 * p + 1], qh, kl[2], kl[3]);
                mma_bf16(s[2 * p + 1], ql, kh[2], kh[3]);
                mma_bf16(s[2 * p + 1], qh, kh[2], kh[3]);
            }
        }

        // ---- scale to base-2, causal mask ----
        if (j0 + 64 > i0 + (wid << 4)) {
#pragma unroll
            for (int nt = 0; nt < 8; nt++) {
                const int col = j0 + (nt << 3) + lc;
                s[nt][0] = (col     > gr    ) ? -1e30f : s[nt][0] * K2;
                s[nt][1] = (col + 1 > gr    ) ? -1e30f : s[nt][1] * K2;
                s[nt][2] = (col     > gr + 8) ? -1e30f : s[nt][2] * K2;
                s[nt][3] = (col + 1 > gr + 8) ? -1e30f : s[nt][3] * K2;
            }
        } else {
#pragma unroll
            for (int nt = 0; nt < 8; nt++)
#pragma unroll
                for (int e = 0; e < 4; e++) s[nt][e] *= K2;
        }

        // ---- online softmax (base-2 domain, FMA-pipe exp) ----
        float rm0 = -1e30f, rm1 = -1e30f;
#pragma unroll
        for (int nt = 0; nt < 8; nt++) {
            rm0 = fmaxf(rm0, fmaxf(s[nt][0], s[nt][1]));
            rm1 = fmaxf(rm1, fmaxf(s[nt][2], s[nt][3]));
        }
        rm0 = fmaxf(rm0, __shfl_xor_sync(0xffffffffu, rm0, 1));
        rm0 = fmaxf(rm0, __shfl_xor_sync(0xffffffffu, rm0, 2));
        rm1 = fmaxf(rm1, __shfl_xor_sync(0xffffffffu, rm1, 1));
        rm1 = fmaxf(rm1, __shfl_xor_sync(0xffffffffu, rm1, 2));
        const float m0n = fmaxf(m0, rm0), m1n = fmaxf(m1, rm1);
        const float c0 = exp2p(m0 - m0n), c1 = exp2p(m1 - m1n);
        m0 = m0n; m1 = m1n;

        float rs0 = 0.f, rs1 = 0.f;
#pragma unroll
        for (int nt = 0; nt < 8; nt++) {
            s[nt][0] = exp2p(s[nt][0] - m0); rs0 += s[nt][0];
            s[nt][1] = exp2p(s[nt][1] - m0); rs0 += s[nt][1];
            s[nt][2] = exp2p(s[nt][2] - m1); rs1 += s[nt][2];
            s[nt][3] = exp2p(s[nt][3] - m1); rs1 += s[nt][3];
        }
        rs0 += __shfl_xor_sync(0xffffffffu, rs0, 1);
        rs0 += __shfl_xor_sync(0xffffffffu, rs0, 2);
        rs1 += __shfl_xor_sync(0xffffffffu, rs1, 1);
        rs1 += __shfl_xor_sync(0xffffffffu, rs1, 2);
        l0 = l0 * c0 + rs0;
        l1 = l1 * c1 + rs1;
#pragma unroll
        for (int nt = 0; nt < 8; nt++) {
            o[nt][0] *= c0; o[nt][1] *= c0;
            o[nt][2] *= c1; o[nt][3] *= c1;
        }

        // ---- O += P V (P in registers; 3-term bf16, ldmatrix V frags) ----
#pragma unroll
        for (int ks = 0; ks < 4; ks++) {
            uint32_t ph[4], pl[4];
            ph[0] = packbf(s[2 * ks][0],     s[2 * ks][1]);
            ph[1] = packbf(s[2 * ks][2],     s[2 * ks][3]);
            ph[2] = packbf(s[2 * ks + 1][0], s[2 * ks + 1][1]);
            ph[3] = packbf(s[2 * ks + 1][2], s[2 * ks + 1][3]);
#pragma unroll
            for (int e = 0; e < 4; e++) {
                const float* sv = s[2 * ks + (e >> 1)];
                const int base = (e & 1) << 1;
                const float f0 = sv[base]     - __uint_as_float(ph[e] << 16);
                const float f1 = sv[base + 1] - __uint_as_float(ph[e] & 0xFFFF0000u);
                pl[e] = packbf(f0, f1);
            }
            const uint32_t kb = ks * 32;
#pragma unroll
            for (int p = 0; p < 4; p++) {
                uint32_t vh[4], vl[4];
                ldsm_x4(vh, uVh + p * (16 * FSTR * 2) + kb);
                ldsm_x4(vl, uVl + p * (16 * FSTR * 2) + kb);
                mma_bf16(o[2 * p],     ph, vl[0], vl[1]);
                mma_bf16(o[2 * p],     pl, vh[0], vh[1]);
                mma_bf16(o[2 * p],     ph, vh[0], vh[1]);
                mma_bf16(o[2 * p + 1], ph, vl[2], vl[3]);
                mma_bf16(o[2 * p + 1], pl, vh[2], vh[3]);
                mma_bf16(o[2 * p + 1], ph, vh[2], vh[3]);
            }
        }
    }

    // ---- finalize + write [b, s, h*HD] ----
    const float inv0 = 1.f / l0, inv1 = 1.f / l1;
#pragma unroll
    for (int nt = 0; nt < 8; nt++) {
        const int d = (nt << 3) + lc;
        float* dst0 = O + ((size_t)b * S_LEN + gr) * (NHQ * HD) + h * HD + d;
        float* dst1 = O + ((size_t)b * S_LEN + gr + 8) * (NHQ * HD) + h * HD + d;
        *(float2*)dst0 = make_float2(o[nt][0] * inv0, o[nt][1] * inv0);
        *(float2*)dst1 = make_float2(o[nt][2] * inv1, o[nt][3] * inv1);
    }
}

// ---------------- launch ----------------
extern "C" void kernel_launch(void* const* d_in, const int* in_sizes, int n_in,
                              void* d_out, int out_size)
{
    const float* X    = (const float*)d_in[0];
    const float* cosb = (const float*)d_in[2];
    const float* sinb = (const float*)d_in[3];
    const float* Wq   = (const float*)d_in[4];
    const float* Wk   = (const float*)d_in[5];
    const float* Wv   = (const float*)d_in[6];
    const float* Wo   = (const float*)d_in[7];
    const float* qw   = (const float*)d_in[8];
    const float* kw   = (const float*)d_in[9];
    float* out = (float*)d_out;

    void *pQ, *pK, *pV, *pA;
    void *pXhi, *pXlo, *pAhi, *pAlo, *pKhi, *pKlo, *pVthi, *pVtlo;
    void *pWq_h, *pWq_l, *pWk_h, *pWk_l, *pWv_h, *pWv_l, *pWo_h, *pWo_l;
    cudaGetSymbolAddress(&pQ, g_Q);
    cudaGetSymbolAddress(&pK, g_K);
    cudaGetSymbolAddress(&pV, g_V);
    cudaGetSymbolAddress(&pA, g_attn);
    cudaGetSymbolAddress(&pXhi, g_Xhi);
    cudaGetSymbolAddress(&pXlo, g_Xlo);
    cudaGetSymbolAddress(&pAhi, g_Ahi);
    cudaGetSymbolAddress(&pAlo, g_Alo);
    cudaGetSymbolAddress(&pKhi, g_Khi);
    cudaGetSymbolAddress(&pKlo, g_Klo);
    cudaGetSymbolAddress(&pVthi, g_Vthi);
    cudaGetSymbolAddress(&pVtlo, g_Vtlo);
    cudaGetSymbolAddress(&pWq_h, g_Wqt_hi);
    cudaGetSymbolAddress(&pWq_l, g_Wqt_lo);
    cudaGetSymbolAddress(&pWk_h, g_Wkt_hi);
    cudaGetSymbolAddress(&pWk_l, g_Wkt_lo);
    cudaGetSymbolAddress(&pWv_h, g_Wvt_hi);
    cudaGetSymbolAddress(&pWv_l, g_Wvt_lo);
    cudaGetSymbolAddress(&pWo_h, g_Wot_hi);
    cudaGetSymbolAddress(&pWo_l, g_Wot_lo);

    cudaFuncSetAttribute(flash_mma_kernel, cudaFuncAttributeMaxDynamicSharedMemorySize, FLASH_SMEM);

    const int M = BATCH * S_LEN;          // 8192
    const int n4 = M * HDIM / 4;

    // input splits / weight transposes
    split_kernel<<<(n4 + 255) / 256, 256>>>(X, (__nv_bfloat16*)pXhi, (__nv_bfloat16*)pXlo, n4);
    transpose_split_kernel<<<dim3(HDIM / 32, HDIM / 32), dim3(32, 8)>>>(Wq, (__nv_bfloat16*)pWq_h, (__nv_bfloat16*)pWq_l, HDIM, HDIM);
    transpose_split_kernel<<<dim3(256 / 32, HDIM / 32), dim3(32, 8)>>>(Wk, (__nv_bfloat16*)pWk_h, (__nv_bfloat16*)pWk_l, HDIM, 256);
    transpose_split_kernel<<<dim3(256 / 32, HDIM / 32), dim3(32, 8)>>>(Wv, (__nv_bfloat16*)pWv_h, (__nv_bfloat16*)pWv_l, HDIM, 256);
    transpose_split_kernel<<<dim3(HDIM / 32, HDIM / 32), dim3(32, 8)>>>(Wo, (__nv_bfloat16*)pWo_h, (__nv_bfloat16*)pWo_l, HDIM, HDIM);

    // QKV projections
    gemm_bf16_kernel<<<dim3(NHQ * HD / 128, M / 128), 256>>>(
        (const __nv_bfloat16*)pXhi, (const __nv_bfloat16*)pXlo,
        (const __nv_bfloat16*)pWq_h, (const __nv_bfloat16*)pWq_l,
        (float*)pQ, NHQ * HD, 1, NHQ);
    gemm_bf16_kernel<<<dim3(NKV * HD / 128, M / 128), 256>>>(
        (const __nv_bfloat16*)pXhi, (const __nv_bfloat16*)pXlo,
        (const __nv_bfloat16*)pWk_h, (const __nv_bfloat16*)pWk_l,
        (float*)pK, NKV * HD, 1, NKV);
    gemm_bf16_kernel<<<dim3(NKV * HD / 128, M / 128), 256>>>(
        (const __nv_bfloat16*)pXhi, (const __nv_bfloat16*)pXlo,
        (const __nv_bfloat16*)pWv_h, (const __nv_bfloat16*)pWv_l,
        (float*)pV, NKV * HD, 1, NKV);

    // RMSNorm + RoPE with fused bf16 hi/lo split
    norm_rope_split_kernel<<<(BATCH * NHQ * S_LEN) / 8, dim3(32, 8)>>>(
        (const float*)pQ, qw, cosb, sinb,
        (__nv_bfloat16*)pAhi, (__nv_bfloat16*)pAlo, BATCH * NHQ * S_LEN);
    norm_rope_split_kernel<<<(BATCH * NKV * S_LEN) / 8, dim3(32, 8)>>>(
        (const float*)pK, kw, cosb, sinb,
        (__nv_bfloat16*)pKhi, (__nv_bfloat16*)pKlo, BATCH * NKV * S_LEN);

    // V transpose + split
    vtrans_split_kernel<<<dim3(S_LEN / 32, HD / 32, BATCH * NKV), dim3(32, 8)>>>(
        (const float*)pV, (__nv_bfloat16*)pVthi, (__nv_bfloat16*)pVtlo);

    // flash attention (tensor-pipe)
    flash_mma_kernel<<<dim3(S_LEN / 128, BATCH * NHQ), 256, FLASH_SMEM>>>(
        (const __nv_bfloat16*)pAhi, (const __nv_bfloat16*)pAlo,
        (const __nv_bfloat16*)pKhi, (const __nv_bfloat16*)pKlo,
        (const __nv_bfloat16*)pVthi, (const __nv_bfloat16*)pVtlo,
        (float*)pA);

    // split attn (reuse Q split buffers), O-projection
    split_kernel<<<(n4 + 255) / 256, 256>>>((const float*)pA, (__nv_bfloat16*)pAhi, (__nv_bfloat16*)pAlo, n4);
    gemm_bf16_kernel<<<dim3(HDIM / 128, M / 128), 256>>>(
        (const __nv_bfloat16*)pAhi, (const __nv_bfloat16*)pAlo,
        (const __nv_bfloat16*)pWo_h, (const __nv_bfloat16*)pWo_l,
        out, HDIM, 0, 0);
}

// round 17
// speedup vs baseline: 2.2985x; 1.1780x over previous
#include <cuda_runtime.h>
#include <cuda_bf16.h>
#include <cstdint>

#define BATCH 4
#define S_LEN 2048
#define HDIM  1024
#define NHQ   16
#define NKV   4
#define HD    64

// ---------------- device scratch (no cudaMalloc allowed) ----------------
__device__ float g_Q[(size_t)BATCH * NHQ * S_LEN * HD];    // [b, h, s, d]
__device__ float g_K[(size_t)BATCH * NKV * S_LEN * HD];    // [b, kvh, s, d]
__device__ float g_V[(size_t)BATCH * NKV * S_LEN * HD];    // [b, kvh, s, d]
__device__ float g_attn[(size_t)BATCH * S_LEN * NHQ * HD]; // [b, s, h*HD]

__device__ __align__(16) __nv_bfloat16 g_Xhi[(size_t)BATCH * S_LEN * HDIM];
__device__ __align__(16) __nv_bfloat16 g_Xlo[(size_t)BATCH * S_LEN * HDIM];
__device__ __align__(16) __nv_bfloat16 g_Ahi[(size_t)BATCH * S_LEN * HDIM];  // Qhi, later attn-hi
__device__ __align__(16) __nv_bfloat16 g_Alo[(size_t)BATCH * S_LEN * HDIM];  // Qlo, later attn-lo
__device__ __align__(16) __nv_bfloat16 g_Khi[(size_t)BATCH * NKV * S_LEN * HD];
__device__ __align__(16) __nv_bfloat16 g_Klo[(size_t)BATCH * NKV * S_LEN * HD];
__device__ __align__(16) __nv_bfloat16 g_Vthi[(size_t)BATCH * NKV * HD * S_LEN]; // [b,kvh,d,s]
__device__ __align__(16) __nv_bfloat16 g_Vtlo[(size_t)BATCH * NKV * HD * S_LEN];
__device__ __align__(16) __nv_bfloat16 g_Wqkvt_hi[(size_t)1536 * HDIM];  // [Wq;Wk;Wv] transposed
__device__ __align__(16) __nv_bfloat16 g_Wqkvt_lo[(size_t)1536 * HDIM];
__device__ __align__(16) __nv_bfloat16 g_Wot_hi[(size_t)HDIM * HDIM];
__device__ __align__(16) __nv_bfloat16 g_Wot_lo[(size_t)HDIM * HDIM];

// ---------------- helpers ----------------
__device__ __forceinline__ uint32_t s2u(const void* p) {
    uint32_t a;
    asm("{ .reg .u64 t; cvta.to.shared.u64 t, %1; cvt.u32.u64 %0, t; }"
        : "=r"(a) : "l"(p));
    return a;
}
__device__ __forceinline__ void ldsm_x4(uint32_t r[4], uint32_t saddr) {
    asm volatile("ldmatrix.sync.aligned.m8n8.x4.shared.b16 {%0,%1,%2,%3}, [%4];"
        : "=r"(r[0]), "=r"(r[1]), "=r"(r[2]), "=r"(r[3]) : "r"(saddr));
}
__device__ __forceinline__ void mma_bf16(float c[4], const uint32_t a[4],
                                         uint32_t b0, uint32_t b1) {
    asm volatile(
        "mma.sync.aligned.m16n8k16.row.col.f32.bf16.bf16.f32 "
        "{%0,%1,%2,%3},{%4,%5,%6,%7},{%8,%9},{%0,%1,%2,%3};"
        : "+f"(c[0]), "+f"(c[1]), "+f"(c[2]), "+f"(c[3])
        : "r"(a[0]), "r"(a[1]), "r"(a[2]), "r"(a[3]), "r"(b0), "r"(b1));
}
__device__ __forceinline__ uint32_t packbf(float lo, float hi) {
    uint32_t r;
    asm("cvt.rn.bf16x2.f32 %0, %1, %2;" : "=r"(r) : "f"(hi), "f"(lo));
    return r;
}
__device__ __forceinline__ void cpa16(uint32_t dst, const void* src) {
    asm volatile("cp.async.cg.shared.global [%0], [%1], 16;" :: "r"(dst), "l"(src));
}
__device__ __forceinline__ void cpa_commit() {
    asm volatile("cp.async.commit_group;" ::: "memory");
}
// 2^x on the FMA pipe, x <= 0 expected; rel err ~1e-4
__device__ __forceinline__ float exp2p(float x) {
    x = fmaxf(x, -126.f);
    const float n = floorf(x);
    const float f = x - n;
    float p = 1.33335581e-3f;
    p = fmaf(p, f, 9.61812910e-3f);
    p = fmaf(p, f, 5.55041087e-2f);
    p = fmaf(p, f, 2.40226507e-1f);
    p = fmaf(p, f, 6.93147182e-1f);
    p = fmaf(p, f, 1.0f);
    return p * __int_as_float(((int)n + 127) << 23);
}

// ---------------- 128x128 GEMM, 3-term bf16, K=1024, cp.async 2-stage ----
#define SSTR 40
#define TILE_HF (128 * SSTR)
#define TILE_BYTES (TILE_HF * 2)        // 10240
#define STAGE_BYTES (4 * TILE_BYTES)    // 40960
#define GEMM_SMEM (2 * STAGE_BYTES)     // 81920

// mode 1: fused QKV scatter (bn<1024 -> Cq heads 16; <1280 -> Ck heads 4; else Cv)
// mode 0: plain row-major MxN into Cq
__global__ __launch_bounds__(256, 2) void gemm_bf16_kernel(
    const __nv_bfloat16* __restrict__ Ahi, const __nv_bfloat16* __restrict__ Alo,
    const __nv_bfloat16* __restrict__ Bhi, const __nv_bfloat16* __restrict__ Blo,
    float* __restrict__ Cq, float* __restrict__ Ck, float* __restrict__ Cv,
    int N, int mode)
{
    extern __shared__ char dsm[];
    const uint32_t sb0 = s2u(dsm);

    const int tid = threadIdx.x;
    const int lane = tid & 31, warp = tid >> 5;
    const int wm = warp & 3, wn = warp >> 2;
    const int bm = blockIdx.y << 7;
    const int bn = blockIdx.x << 7;

    // ldmatrix lane offsets (within a stage, bytes)
    const uint32_t aRow = wm * 32 + (lane & 15);
    const uint32_t aColH = (lane >> 4) << 3;
    const uint32_t offA = (aRow * SSTR + aColH) * 2;
    const uint32_t bRow = wn * 64 + (lane & 7) + (((lane >> 4) & 1) << 3);
    const uint32_t bColH = ((lane >> 3) & 1) << 3;
    const uint32_t offB = (bRow * SSTR + bColH) * 2;

    float acc[2][8][4];
#pragma unroll
    for (int mt = 0; mt < 2; mt++)
#pragma unroll
        for (int nt = 0; nt < 8; nt++)
#pragma unroll
            for (int e = 0; e < 4; e++) acc[mt][nt][e] = 0.f;

    // staging: seg = tid + 256*i; row = seg>>2; scol = (seg&3)*8 halfwords
    auto stage = [&](int c, int buf) {
        const int k0 = c << 5;
        const uint32_t sb = sb0 + buf * STAGE_BYTES;
#pragma unroll
        for (int i = 0; i < 2; i++) {
            const int seg = tid + (i << 8);
            const int row = seg >> 2;
            const int scol = (seg & 3) << 3;
            const uint32_t d = sb + (uint32_t)(row * SSTR + scol) * 2;
            const size_t ga = (size_t)(bm + row) * HDIM + k0 + scol;
            const size_t gb = (size_t)(bn + row) * HDIM + k0 + scol;
            cpa16(d,                  Ahi + ga);
            cpa16(d + TILE_BYTES,     Alo + ga);
            cpa16(d + 2 * TILE_BYTES, Bhi + gb);
            cpa16(d + 3 * TILE_BYTES, Blo + gb);
        }
        cpa_commit();
    };

    stage(0, 0);

    for (int c = 0; c < 32; c++) {
        if (c < 31) {
            stage(c + 1, (c + 1) & 1);
            asm volatile("cp.async.wait_group 1;" ::: "memory");
        } else {
            asm volatile("cp.async.wait_group 0;" ::: "memory");
        }
        __syncthreads();

        const uint32_t sbuf = sb0 + (c & 1) * STAGE_BYTES;
        const uint32_t uAh = sbuf + offA;
        const uint32_t uAl = uAh + TILE_BYTES;
        const uint32_t uBh = sbuf + 2 * TILE_BYTES + offB;
        const uint32_t uBl = uBh + TILE_BYTES;
#pragma unroll
        for (int ks = 0; ks < 2; ks++) {
            const uint32_t kb = ks * 32;
            uint32_t ah[2][4], al[2][4];
            ldsm_x4(ah[0], uAh + kb); ldsm_x4(ah[1], uAh + 16 * SSTR * 2 + kb);
            ldsm_x4(al[0], uAl + kb); ldsm_x4(al[1], uAl + 16 * SSTR * 2 + kb);
#pragma unroll
            for (int p = 0; p < 4; p++) {
                uint32_t bh[4], bl[4];
                ldsm_x4(bh, uBh + p * (16 * SSTR * 2) + kb);
                ldsm_x4(bl, uBl + p * (16 * SSTR * 2) + kb);
#pragma unroll
                for (int mt = 0; mt < 2; mt++) {
                    mma_bf16(acc[mt][2 * p],     ah[mt], bl[0], bl[1]);
                    mma_bf16(acc[mt][2 * p],     al[mt], bh[0], bh[1]);
                    mma_bf16(acc[mt][2 * p],     ah[mt], bh[0], bh[1]);
                    mma_bf16(acc[mt][2 * p + 1], ah[mt], bl[2], bl[3]);
                    mma_bf16(acc[mt][2 * p + 1], al[mt], bh[2], bh[3]);
                    mma_bf16(acc[mt][2 * p + 1], ah[mt], bh[2], bh[3]);
                }
            }
        }
        __syncthreads();
    }

    // epilogue
    float* Cb = Cq;
    int coff = bn, Hr = NHQ;
    if (mode == 1) {
        if (bn >= 1280)      { Cb = Cv; coff = bn - 1280; Hr = NKV; }
        else if (bn >= 1024) { Cb = Ck; coff = bn - 1024; Hr = NKV; }
    }
#pragma unroll
    for (int mt = 0; mt < 2; mt++) {
#pragma unroll
        for (int nt = 0; nt < 8; nt++) {
            const int r0 = bm + wm * 32 + mt * 16 + (lane >> 2);
            const int cn = coff + wn * 64 + nt * 8 + (lane & 3) * 2;
            if (mode == 1) {
                const int head = cn >> 6, d = cn & 63;
#pragma unroll
                for (int half = 0; half < 2; half++) {
                    const int rm = r0 + half * 8;
                    const int b = rm >> 11, s = rm & 2047;
                    float* dst = Cb + (((size_t)(b * Hr + head)) * S_LEN + s) * HD + d;
                    *(float2*)dst = make_float2(acc[mt][nt][half * 2], acc[mt][nt][half * 2 + 1]);
                }
            } else {
                *(float2*)(Cb + (size_t)r0 * N + cn) =
                    make_float2(acc[mt][nt][0], acc[mt][nt][1]);
                *(float2*)(Cb + (size_t)(r0 + 8) * N + cn) =
                    make_float2(acc[mt][nt][2], acc[mt][nt][3]);
            }
        }
    }
}

// ---------------- fp32 -> bf16 hi/lo split ----------------
__global__ __launch_bounds__(256) void split_kernel(
    const float* __restrict__ X, __nv_bfloat16* __restrict__ Hi,
    __nv_bfloat16* __restrict__ Lo, int n4)
{
    const int i = blockIdx.x * 256 + threadIdx.x;
    if (i >= n4) return;
    const float4 v = ((const float4*)X)[i];
    float x[4] = {v.x, v.y, v.z, v.w};
    __nv_bfloat16 h[4], l[4];
#pragma unroll
    for (int e = 0; e < 4; e++) {
        h[e] = __float2bfloat16(x[e]);
        l[e] = __float2bfloat16(x[e] - __bfloat162float(h[e]));
    }
    ((__nv_bfloat162*)Hi)[2 * i]     = __nv_bfloat162(h[0], h[1]);
    ((__nv_bfloat162*)Hi)[2 * i + 1] = __nv_bfloat162(h[2], h[3]);
    ((__nv_bfloat162*)Lo)[2 * i]     = __nv_bfloat162(l[0], l[1]);
    ((__nv_bfloat162*)Lo)[2 * i + 1] = __nv_bfloat162(l[2], l[3]);
}

// ---------------- W[K,N] fp32 -> Wt[N+row_off, K] bf16 hi/lo --------------
__global__ __launch_bounds__(256) void transpose_split_kernel(
    const float* __restrict__ W, __nv_bfloat16* __restrict__ Thi,
    __nv_bfloat16* __restrict__ Tlo, int K, int N, int row_off)
{
    __shared__ float t[32][33];
    const int k0 = blockIdx.y * 32, n0 = blockIdx.x * 32;
    const int tx = threadIdx.x, ty = threadIdx.y;
#pragma unroll
    for (int i = 0; i < 32; i += 8)
        t[ty + i][tx] = W[(size_t)(k0 + ty + i) * N + n0 + tx];
    __syncthreads();
#pragma unroll
    for (int i = 0; i < 32; i += 8) {
        const float x = t[tx][ty + i];
        const __nv_bfloat16 h = __float2bfloat16(x);
        const __nv_bfloat16 l = __float2bfloat16(x - __bfloat162float(h));
        Thi[(size_t)(row_off + n0 + ty + i) * K + k0 + tx] = h;
        Tlo[(size_t)(row_off + n0 + ty + i) * K + k0 + tx] = l;
    }
}

// ---------------- V [bk,s,d] fp32 -> Vt [bk,d,s] bf16 hi/lo ----------------
__global__ __launch_bounds__(256) void vtrans_split_kernel(
    const float* __restrict__ V, __nv_bfloat16* __restrict__ Thi,
    __nv_bfloat16* __restrict__ Tlo)
{
    __shared__ float t[32][33];
    const int s0 = blockIdx.x << 5, d0 = blockIdx.y << 5;
    const int bk = blockIdx.z;
    const int tx = threadIdx.x, ty = threadIdx.y;
    const float* src = V + (size_t)bk * S_LEN * HD;
#pragma unroll
    for (int i = 0; i < 32; i += 8)
        t[ty + i][tx] = src[(size_t)(s0 + ty + i) * HD + d0 + tx];
    __syncthreads();
    __nv_bfloat16* dh = Thi + (size_t)bk * HD * S_LEN;
    __nv_bfloat16* dl = Tlo + (size_t)bk * HD * S_LEN;
#pragma unroll
    for (int i = 0; i < 32; i += 8) {
        const float x = t[tx][ty + i];
        const __nv_bfloat16 h = __float2bfloat16(x);
        const __nv_bfloat16 l = __float2bfloat16(x - __bfloat162float(h));
        dh[(size_t)(d0 + ty + i) * S_LEN + s0 + tx] = h;
        dl[(size_t)(d0 + ty + i) * S_LEN + s0 + tx] = l;
    }
}

// ---------------- RMSNorm + RoPE, output split bf16 hi/lo ----------------
__global__ __launch_bounds__(256) void norm_rope_split_kernel(
    const float* __restrict__ X, const float* __restrict__ w,
    const float* __restrict__ cosb, const float* __restrict__ sinb,
    __nv_bfloat16* __restrict__ Hi, __nv_bfloat16* __restrict__ Lo, int rows)
{
    const int row = blockIdx.x * 8 + threadIdx.y;
    if (row >= rows) return;
    const int lane = threadIdx.x;
    const int s = row & (S_LEN - 1);

    float2 x = *(const float2*)(X + (size_t)row * HD + lane * 2);
    float ssq = x.x * x.x + x.y * x.y;
#pragma unroll
    for (int m = 16; m; m >>= 1) ssq += __shfl_xor_sync(0xffffffffu, ssq, m);
    const float inv = rsqrtf(ssq * (1.0f / 64.0f) + 1e-6f);

    const float n0 = x.x * inv * w[lane * 2];
    const float n1 = x.y * inv * w[lane * 2 + 1];
    const float c0 = cosb[(size_t)s * HD + lane * 2];
    const float c1 = cosb[(size_t)s * HD + lane * 2 + 1];
    const float s0 = sinb[(size_t)s * HD + lane * 2];
    const float s1 = sinb[(size_t)s * HD + lane * 2 + 1];

    const float ox = n0 * c0 - n1 * s0;
    const float oy = n1 * c1 + n0 * s1;

    const __nv_bfloat16 hx = __float2bfloat16(ox);
    const __nv_bfloat16 hy = __float2bfloat16(oy);
    const __nv_bfloat16 lx = __float2bfloat16(ox - __bfloat162float(hx));
    const __nv_bfloat16 ly = __float2bfloat16(oy - __bfloat162float(hy));
    *(__nv_bfloat162*)(Hi + (size_t)row * HD + lane * 2) = __nv_bfloat162(hx, hy);
    *(__nv_bfloat162*)(Lo + (size_t)row * HD + lane * 2) = __nv_bfloat162(lx, ly);
}

// ---------------- flash attention via bf16 mma (causal, GQA) --------------
#define FSTR 72
#define QT_HF (128 * FSTR)
#define KT_HF (64 * FSTR)
#define KT_BYTES (KT_HF * 2)                 // 9216
#define KV_STAGE_BYTES (4 * KT_BYTES)        // 36864
#define FLASH_SMEM ((2 * QT_HF) * 2 + 2 * KV_STAGE_BYTES)   // 110592 B

__global__ __launch_bounds__(256) void flash_mma_kernel(
    const __nv_bfloat16* __restrict__ Qhi, const __nv_bfloat16* __restrict__ Qlo,
    const __nv_bfloat16* __restrict__ Khi, const __nv_bfloat16* __restrict__ Klo,
    const __nv_bfloat16* __restrict__ Vhi, const __nv_bfloat16* __restrict__ Vlo,
    float* __restrict__ O)
{
    extern __shared__ __nv_bfloat16 sm[];
    __nv_bfloat16* sQh = sm;
    __nv_bfloat16* sQl = sQh + QT_HF;
    const uint32_t sKV0 = s2u(sQl + QT_HF);

    const int tid = threadIdx.x, lane = tid & 31, wid = tid >> 5;
    const int ib = (int)gridDim.x - 1 - (int)blockIdx.x;   // heavy blocks first
    const int bh = blockIdx.y;
    const int b = bh >> 4, h = bh & 15, kvh = (bh & 15) >> 2;
    const int i0 = ib << 7;

    const __nv_bfloat16* Qhb = Qhi + ((size_t)(b * NHQ + h) * S_LEN + i0) * HD;
    const __nv_bfloat16* Qlb = Qlo + ((size_t)(b * NHQ + h) * S_LEN + i0) * HD;
    const __nv_bfloat16* Khb = Khi + (size_t)(b * NKV + kvh) * S_LEN * HD;
    const __nv_bfloat16* Klb = Klo + (size_t)(b * NKV + kvh) * S_LEN * HD;
    const __nv_bfloat16* Vhb = Vhi + (size_t)(b * NKV + kvh) * HD * S_LEN;
    const __nv_bfloat16* Vlb = Vlo + (size_t)(b * NKV + kvh) * HD * S_LEN;

    // KV staging via cp.async (2 stages)
    auto stageKV = [&](int t, int buf) {
        const int j0 = t << 6;
        const uint32_t sb = sKV0 + buf * KV_STAGE_BYTES;
#pragma unroll
        for (int i = 0; i < 2; i++) {
            const int seg = tid + (i << 8);
            const int r = seg >> 3;
            const int sc_ = (seg & 7) << 3;
            const uint32_t d = sb + (uint32_t)(r * FSTR + sc_) * 2;
            cpa16(d,                Khb + (size_t)(j0 + r) * HD + sc_);
            cpa16(d + KT_BYTES,     Klb + (size_t)(j0 + r) * HD + sc_);
            cpa16(d + 2 * KT_BYTES, Vhb + (size_t)r * S_LEN + j0 + sc_);
            cpa16(d + 3 * KT_BYTES, Vlb + (size_t)r * S_LEN + j0 + sc_);
        }
        cpa_commit();
    };

    stageKV(0, 0);

    // load Q tile (plain; overlaps with cp.async)
    for (int it = tid; it < 1024; it += 256) {
        const int r = it >> 3, j = (it & 7) << 3;
        *(uint4*)&sQh[r * FSTR + j] = *(const uint4*)(Qhb + (size_t)r * HD + j);
        *(uint4*)&sQl[r * FSTR + j] = *(const uint4*)(Qlb + (size_t)r * HD + j);
    }

    const int lr = lane >> 2, lc = (lane & 3) << 1;
    const int gr = i0 + (wid << 4) + lr;

    // ldmatrix lane offsets
    const uint32_t qRow = (wid << 4) + (lane & 15);
    const uint32_t colH = (lane >> 4) << 3;
    const uint32_t uQh = s2u(sQh) + (qRow * FSTR + colH) * 2;
    const uint32_t uQl = s2u(sQl) + (qRow * FSTR + colH) * 2;
    const uint32_t bRow = (lane & 7) + (((lane >> 4) & 1) << 3);
    const uint32_t bColH = ((lane >> 3) & 1) << 3;
    const uint32_t offKV = (bRow * FSTR + bColH) * 2;

    float m0 = -1e30f, m1 = -1e30f, l0 = 0.f, l1 = 0.f;
    float o[8][4];
#pragma unroll
    for (int nt = 0; nt < 8; nt++)
#pragma unroll
        for (int e = 0; e < 4; e++) o[nt][e] = 0.f;

    const float K2 = 0.1803368801f;   // 0.125 * log2(e)
    const int ntiles = 2 * ib + 2;

    for (int t = 0; t < ntiles; t++) {
        const int j0 = t << 6;
        if (t + 1 < ntiles) {
            stageKV(t + 1, (t + 1) & 1);
            asm volatile("cp.async.wait_group 1;" ::: "memory");
        } else {
            asm volatile("cp.async.wait_group 0;" ::: "memory");
        }
        __syncthreads();

        const uint32_t sb = sKV0 + (t & 1) * KV_STAGE_BYTES;
        const uint32_t uKh = sb + offKV;
        const uint32_t uKl = uKh + KT_BYTES;
        const uint32_t uVh = sb + 2 * KT_BYTES + offKV;
        const uint32_t uVl = uVh + KT_BYTES;

        // ---- S = Q K^T (3-term bf16, ldmatrix frags) ----
        float s[8][4];
#pragma unroll
        for (int nt = 0; nt < 8; nt++)
#pragma unroll
            for (int e = 0; e < 4; e++) s[nt][e] = 0.f;

#pragma unroll
        for (int ks = 0; ks < 4; ks++) {
            const uint32_t kb = ks * 32;
            uint32_t qh[4], ql[4];
            ldsm_x4(qh, uQh + kb);
            ldsm_x4(ql, uQl + kb);
#pragma unroll
            for (int p = 0; p < 4; p++) {
                uint32_t kh[4], kl[4];
                ldsm_x4(kh, uKh + p * (16 * FSTR * 2) + kb);
                ldsm_x4(kl, uKl + p * (16 * FSTR * 2) + kb);
                mma_bf16(s[2 * p],     qh, kl[0], kl[1]);
                mma_bf16(s[2 * p],     ql, kh[0], kh[1]);
                mma_bf16(s[2 * p],     qh, kh[0], kh[1]);
                mma_bf16(s[2 * p + 1], qh, kl[2], kl[3]);
                mma_bf16(s[2 * p + 1], ql, kh[2], kh[3]);
                mma_bf16(s[2 * p + 1], qh, kh[2], kh[3]);
            }
        }

        // ---- scale to base-2, causal mask ----
        if (j0 + 64 > i0 + (wid << 4)) {
#pragma unroll
            for (int nt = 0; nt < 8; nt++) {
                const int col = j0 + (nt << 3) + lc;
                s[nt][0] = (col     > gr    ) ? -1e30f : s[nt][0] * K2;
                s[nt][1] = (col + 1 > gr    ) ? -1e30f : s[nt][1] * K2;
                s[nt][2] = (col     > gr + 8) ? -1e30f : s[nt][2] * K2;
                s[nt][3] = (col + 1 > gr + 8) ? -1e30f : s[nt][3] * K2;
            }
        } else {
#pragma unroll
            for (int nt = 0; nt < 8; nt++)
#pragma unroll
                for (int e = 0; e < 4; e++) s[nt][e] *= K2;
        }

        // ---- online softmax (base-2 domain, FMA-pipe exp) ----
        float rm0 = -1e30f, rm1 = -1e30f;
#pragma unroll
        for (int nt = 0; nt < 8; nt++) {
            rm0 = fmaxf(rm0, fmaxf(s[nt][0], s[nt][1]));
            rm1 = fmaxf(rm1, fmaxf(s[nt][2], s[nt][3]));
        }
        rm0 = fmaxf(rm0, __shfl_xor_sync(0xffffffffu, rm0, 1));
        rm0 = fmaxf(rm0, __shfl_xor_sync(0xffffffffu, rm0, 2));
        rm1 = fmaxf(rm1, __shfl_xor_sync(0xffffffffu, rm1, 1));
        rm1 = fmaxf(rm1, __shfl_xor_sync(0xffffffffu, rm1, 2));
        const float m0n = fmaxf(m0, rm0), m1n = fmaxf(m1, rm1);
        const float c0 = exp2p(m0 - m0n), c1 = exp2p(m1 - m1n);
        m0 = m0n; m1 = m1n;

        float rs0 = 0.f, rs1 = 0.f;
#pragma unroll
        for (int nt = 0; nt < 8; nt++) {
            s[nt][0] = exp2p(s[nt][0] - m0); rs0 += s[nt][0];
            s[nt][1] = exp2p(s[nt][1] - m0); rs0 += s[nt][1];
            s[nt][2] = exp2p(s[nt][2] - m1); rs1 += s[nt][2];
            s[nt][3] = exp2p(s[nt][3] - m1); rs1 += s[nt][3];
        }
        rs0 += __shfl_xor_sync(0xffffffffu, rs0, 1);
        rs0 += __shfl_xor_sync(0xffffffffu, rs0, 2);
        rs1 += __shfl_xor_sync(0xffffffffu, rs1, 1);
        rs1 += __shfl_xor_sync(0xffffffffu, rs1, 2);
        l0 = l0 * c0 + rs0;
        l1 = l1 * c1 + rs1;
#pragma unroll
        for (int nt = 0; nt < 8; nt++) {
            o[nt][0] *= c0; o[nt][1] *= c0;
            o[nt][2] *= c1; o[nt][3] *= c1;
        }

        // ---- O += P V (P in registers; 3-term bf16, ldmatrix V frags) ----
#pragma unroll
        for (int ks = 0; ks < 4; ks++) {
            uint32_t ph[4], pl[4];
            ph[0] = packbf(s[2 * ks][0],     s[2 * ks][1]);
            ph[1] = packbf(s[2 * ks][2],     s[2 * ks][3]);
            ph[2] = packbf(s[2 * ks + 1][0], s[2 * ks + 1][1]);
            ph[3] = packbf(s[2 * ks + 1][2], s[2 * ks + 1][3]);
#pragma unroll
            for (int e = 0; e < 4; e++) {
                const float* sv = s[2 * ks + (e >> 1)];
                const int base = (e & 1) << 1;
                const float f0 = sv[base]     - __uint_as_float(ph[e] << 16);
                const float f1 = sv[base + 1] - __uint_as_float(ph[e] & 0xFFFF0000u);
                pl[e] = packbf(f0, f1);
            }
            const uint32_t kb = ks * 32;
#pragma unroll
            for (int p = 0; p < 4; p++) {
                uint32_t vh[4], vl[4];
                ldsm_x4(vh, uVh + p * (16 * FSTR * 2) + kb);
                ldsm_x4(vl, uVl + p * (16 * FSTR * 2) + kb);
                mma_bf16(o[2 * p],     ph, vl[0], vl[1]);
                mma_bf16(o[2 * p],     pl, vh[0], vh[1]);
                mma_bf16(o[2 * p],     ph, vh[0], vh[1]);
                mma_bf16(o[2 * p + 1], ph, vl[2], vl[3]);
                mma_bf16(o[2 * p + 1], pl, vh[2], vh[3]);
                mma_bf16(o[2 * p + 1], ph, vh[2], vh[3]);
            }
        }
        __syncthreads();
    }

    // ---- finalize + write [b, s, h*HD] ----
    const float inv0 = 1.f / l0, inv1 = 1.f / l1;
#pragma unroll
    for (int nt = 0; nt < 8; nt++) {
        const int d = (nt << 3) + lc;
        float* dst0 = O + ((size_t)b * S_LEN + gr) * (NHQ * HD) + h * HD + d;
        float* dst1 = O + ((size_t)b * S_LEN + gr + 8) * (NHQ * HD) + h * HD + d;
        *(float2*)dst0 = make_float2(o[nt][0] * inv0, o[nt][1] * inv0);
        *(float2*)dst1 = make_float2(o[nt][2] * inv1, o[nt][3] * inv1);
    }
}

// ---------------- launch ----------------
extern "C" void kernel_launch(void* const* d_in, const int* in_sizes, int n_in,
                              void* d_out, int out_size)
{
    const float* X    = (const float*)d_in[0];
    const float* cosb = (const float*)d_in[2];
    const float* sinb = (const float*)d_in[3];
    const float* Wq   = (const float*)d_in[4];
    const float* Wk   = (const float*)d_in[5];
    const float* Wv   = (const float*)d_in[6];
    const float* Wo   = (const float*)d_in[7];
    const float* qw   = (const float*)d_in[8];
    const float* kw   = (const float*)d_in[9];
    float* out = (float*)d_out;

    void *pQ, *pK, *pV, *pA;
    void *pXhi, *pXlo, *pAhi, *pAlo, *pKhi, *pKlo, *pVthi, *pVtlo;
    void *pWqkv_h, *pWqkv_l, *pWo_h, *pWo_l;
    cudaGetSymbolAddress(&pQ, g_Q);
    cudaGetSymbolAddress(&pK, g_K);
    cudaGetSymbolAddress(&pV, g_V);
    cudaGetSymbolAddress(&pA, g_attn);
    cudaGetSymbolAddress(&pXhi, g_Xhi);
    cudaGetSymbolAddress(&pXlo, g_Xlo);
    cudaGetSymbolAddress(&pAhi, g_Ahi);
    cudaGetSymbolAddress(&pAlo, g_Alo);
    cudaGetSymbolAddress(&pKhi, g_Khi);
    cudaGetSymbolAddress(&pKlo, g_Klo);
    cudaGetSymbolAddress(&pVthi, g_Vthi);
    cudaGetSymbolAddress(&pVtlo, g_Vtlo);
    cudaGetSymbolAddress(&pWqkv_h, g_Wqkvt_hi);
    cudaGetSymbolAddress(&pWqkv_l, g_Wqkvt_lo);
    cudaGetSymbolAddress(&pWo_h, g_Wot_hi);
    cudaGetSymbolAddress(&pWo_l, g_Wot_lo);

    cudaFuncSetAttribute(gemm_bf16_kernel, cudaFuncAttributeMaxDynamicSharedMemorySize, GEMM_SMEM);
    cudaFuncSetAttribute(flash_mma_kernel, cudaFuncAttributeMaxDynamicSharedMemorySize, FLASH_SMEM);

    const int M = BATCH * S_LEN;          // 8192
    const int n4 = M * HDIM / 4;

    // input split / weight transposes (QKV concatenated)
    split_kernel<<<(n4 + 255) / 256, 256>>>(X, (__nv_bfloat16*)pXhi, (__nv_bfloat16*)pXlo, n4);
    transpose_split_kernel<<<dim3(HDIM / 32, HDIM / 32), dim3(32, 8)>>>(Wq, (__nv_bfloat16*)pWqkv_h, (__nv_bfloat16*)pWqkv_l, HDIM, HDIM, 0);
    transpose_split_kernel<<<dim3(256 / 32, HDIM / 32), dim3(32, 8)>>>(Wk, (__nv_bfloat16*)pWqkv_h, (__nv_bfloat16*)pWqkv_l, HDIM, 256, 1024);
    transpose_split_kernel<<<dim3(256 / 32, HDIM / 32), dim3(32, 8)>>>(Wv, (__nv_bfloat16*)pWqkv_h, (__nv_bfloat16*)pWqkv_l, HDIM, 256, 1280);
    transpose_split_kernel<<<dim3(HDIM / 32, HDIM / 32), dim3(32, 8)>>>(Wo, (__nv_bfloat16*)pWo_h, (__nv_bfloat16*)pWo_l, HDIM, HDIM, 0);

    // fused QKV projection (one launch, scatter per region)
    gemm_bf16_kernel<<<dim3(1536 / 128, M / 128), 256, GEMM_SMEM>>>(
        (const __nv_bfloat16*)pXhi, (const __nv_bfloat16*)pXlo,
        (const __nv_bfloat16*)pWqkv_h, (const __nv_bfloat16*)pWqkv_l,
        (float*)pQ, (float*)pK, (float*)pV, 0, 1);

    // RMSNorm + RoPE with fused bf16 hi/lo split
    norm_rope_split_kernel<<<(BATCH * NHQ * S_LEN) / 8, dim3(32, 8)>>>(
        (const float*)pQ, qw, cosb, sinb,
        (__nv_bfloat16*)pAhi, (__nv_bfloat16*)pAlo, BATCH * NHQ * S_LEN);
    norm_rope_split_kernel<<<(BATCH * NKV * S_LEN) / 8, dim3(32, 8)>>>(
        (const float*)pK, kw, cosb, sinb,
        (__nv_bfloat16*)pKhi, (__nv_bfloat16*)pKlo, BATCH * NKV * S_LEN);

    // V transpose + split
    vtrans_split_kernel<<<dim3(S_LEN / 32, HD / 32, BATCH * NKV), dim3(32, 8)>>>(
        (const float*)pV, (__nv_bfloat16*)pVthi, (__nv_bfloat16*)pVtlo);

    // flash attention (tensor-pipe, cp.async pipelined)
    flash_mma_kernel<<<dim3(S_LEN / 128, BATCH * NHQ), 256, FLASH_SMEM>>>(
        (const __nv_bfloat16*)pAhi, (const __nv_bfloat16*)pAlo,
        (const __nv_bfloat16*)pKhi, (const __nv_bfloat16*)pKlo,
        (const __nv_bfloat16*)pVthi, (const __nv_bfloat16*)pVtlo,
        (float*)pA);

    // split attn (reuse Q split buffers), O-projection
    split_kernel<<<(n4 + 255) / 256, 256>>>((const float*)pA, (__nv_bfloat16*)pAhi, (__nv_bfloat16*)pAlo, n4);
    gemm_bf16_kernel<<<dim3(HDIM / 128, M / 128), 256, GEMM_SMEM>>>(
        (const __nv_bfloat16*)pAhi, (const __nv_bfloat16*)pAlo,
        (const __nv_bfloat16*)pWo_h, (const __nv_bfloat16*)pWo_l,
        out, nullptr, nullptr, HDIM, 0);
}